// round 9
// baseline (speedup 1.0000x reference)
#include <cuda_runtime.h>
#include <cuda_bf16.h>
#include <math.h>

// ---------------- problem constants ----------------
#define NB    32
#define LSEQ  192
#define SEQF  193
#define DM    384
#define DI    768
#define DS    16
#define DTRK  24
#define XPD   56
#define ROWS  (NB*LSEQ)   // 6144

// ---------------- scratch (floats) ----------------
__device__ float g_scratch[43696128];

#define OFF_PR     0
#define OFF_XZ     2359296
#define OFF_XC     11796480
#define OFF_XDBL   16515072
#define OFF_DT     16859136
#define OFF_FUSED  21577728
#define OFF_ACT3   23937024
#define OFF_CAT3   31014912
#define OFF_W3     38092800

// ---------------- gather ----------------
__global__ void gather_kernel(const float* __restrict__ X,
                              const int* __restrict__ scan_idx,
                              float* __restrict__ PR)
{
    int idx = blockIdx.x * blockDim.x + threadIdx.x;
    if (idx >= ROWS * DM) return;
    int c = idx % DM;
    int t = (idx / DM) % LSEQ;
    int b = idx / (DM * LSEQ);
    int src = scan_idx[t];
    PR[idx] = X[((size_t)b * SEQF + 1 + src) * DM + c];
}

// ---------------- layernorm fused with 3-block bf16 split ----------------
__global__ __launch_bounds__(128) void ln_split_kernel(
    const float* __restrict__ X,
    const float* __restrict__ G,
    const float* __restrict__ Bb,
    __nv_bfloat16* __restrict__ A3)
{
    int row = blockIdx.x;
    const float* x = X + (size_t)row * DM;
    float v[3]; float s = 0.f, ss = 0.f;
    #pragma unroll
    for (int i = 0; i < 3; i++) {
        v[i] = x[threadIdx.x + i * 128];
        s += v[i]; ss += v[i] * v[i];
    }
    __shared__ float sh_s[4], sh_ss[4];
    #pragma unroll
    for (int o = 16; o; o >>= 1) {
        s  += __shfl_down_sync(0xffffffffu, s,  o);
        ss += __shfl_down_sync(0xffffffffu, ss, o);
    }
    int wid = threadIdx.x >> 5, lid = threadIdx.x & 31;
    if (lid == 0) { sh_s[wid] = s; sh_ss[wid] = ss; }
    __syncthreads();
    float ts = sh_s[0] + sh_s[1] + sh_s[2] + sh_s[3];
    float tss = sh_ss[0] + sh_ss[1] + sh_ss[2] + sh_ss[3];
    float mean = ts * (1.f / DM);
    float var = tss * (1.f / DM) - mean * mean;
    float rstd = rsqrtf(var + 1e-5f);
    __nv_bfloat16* a = A3 + (size_t)row * (3 * DM);
    #pragma unroll
    for (int i = 0; i < 3; i++) {
        int c = threadIdx.x + i * 128;
        float y = (v[i] - mean) * rstd * G[c] + Bb[c];
        __nv_bfloat16 hi = __float2bfloat16(y);
        __nv_bfloat16 lo = __float2bfloat16(y - __bfloat162float(hi));
        a[c]          = hi;
        a[DM + c]     = hi;
        a[2 * DM + c] = lo;
    }
}

// ---------------- weight 3-block split: Y[n, 3K] = [hi | lo | hi] ----------------
__global__ void split3_wt(const float* __restrict__ X,
                          __nv_bfloat16* __restrict__ Y,
                          int total, int K)
{
    int idx = blockIdx.x * blockDim.x + threadIdx.x;
    if (idx >= total) return;
    int m = idx / K, k = idx % K;
    float x = X[idx];
    __nv_bfloat16 hi = __float2bfloat16(x);
    __nv_bfloat16 lo = __float2bfloat16(x - __bfloat162float(hi));
    size_t r = (size_t)m * (3 * K);
    Y[r + k]         = hi;
    Y[r + K + k]     = lo;
    Y[r + 2 * K + k] = hi;
}

// ---------------- mma / cp.async helpers ----------------
__device__ __forceinline__ void mma16816(float* c, const unsigned* a, const unsigned* b)
{
    asm volatile(
        "mma.sync.aligned.m16n8k16.row.col.f32.bf16.bf16.f32 "
        "{%0,%1,%2,%3}, {%4,%5,%6,%7}, {%8,%9}, {%0,%1,%2,%3};\n"
        : "+f"(c[0]), "+f"(c[1]), "+f"(c[2]), "+f"(c[3])
        : "r"(a[0]), "r"(a[1]), "r"(a[2]), "r"(a[3]), "r"(b[0]), "r"(b[1]));
}
__device__ __forceinline__ void ldsmx4(unsigned* r, unsigned addr)
{
    asm volatile("ldmatrix.sync.aligned.m8n8.x4.shared.b16 {%0,%1,%2,%3}, [%4];"
                 : "=r"(r[0]), "=r"(r[1]), "=r"(r[2]), "=r"(r[3]) : "r"(addr));
}
__device__ __forceinline__ void ldsmx2(unsigned* r, unsigned addr)
{
    asm volatile("ldmatrix.sync.aligned.m8n8.x2.shared.b16 {%0,%1}, [%2];"
                 : "=r"(r[0]), "=r"(r[1]) : "r"(addr));
}
__device__ __forceinline__ void cpa16(unsigned dst, const void* src)
{
    asm volatile("cp.async.cg.shared.global [%0], [%1], 16;\n" :: "r"(dst), "l"(src));
}
__device__ __forceinline__ void cpa_commit()
{
    asm volatile("cp.async.commit_group;\n");
}
template<int N>
__device__ __forceinline__ void cpa_wait()
{
    asm volatile("cp.async.wait_group %0;\n" :: "n"(N));
}

// split-bf16 store for out_proj epilogue (cat3 row = 2304 bf16: [hi|hi|lo])
__device__ __forceinline__ void split_store2(__nv_bfloat16* C3, int row, int colL,
                                             float s0, float s1)
{
    __nv_bfloat16 h0 = __float2bfloat16(s0);
    __nv_bfloat16 h1 = __float2bfloat16(s1);
    __nv_bfloat16 l0 = __float2bfloat16(s0 - __bfloat162float(h0));
    __nv_bfloat16 l1 = __float2bfloat16(s1 - __bfloat162float(h1));
    __nv_bfloat162 hp; hp.x = h0; hp.y = h1;
    __nv_bfloat162 lp; lp.x = l0; lp.y = l1;
    size_t rb = (size_t)row * 2304;
    *(__nv_bfloat162*)&C3[rb + colL]        = hp;
    *(__nv_bfloat162*)&C3[rb + 768 + colL]  = hp;
    *(__nv_bfloat162*)&C3[rb + 1536 + colL] = lp;
}

// ---------------- 3-stage pipelined bf16 tensor GEMM, BN=128 ----------------
// EPI: 0 none (fp32 C), 1 +bias (fp32 C), 3 +residual then split-bf16 store to C3
#define SKS 40
#define TILEB (128 * SKS * 2)
#define STAGES 3
template<int EPI>
__global__ __launch_bounds__(256, 2) void bgemm(
    const __nv_bfloat16* __restrict__ A2, int lda,
    const __nv_bfloat16* __restrict__ W2, int K2,
    const float* __restrict__ bias,
    const float* __restrict__ R, int ldr,
    float* __restrict__ C, int ldc,
    __nv_bfloat16* __restrict__ C3, int dirOff)
{
    extern __shared__ __nv_bfloat16 dsm[];
    __nv_bfloat16* Asm = dsm;
    __nv_bfloat16* Wsm = dsm + STAGES * 128 * SKS;

    int tid = threadIdx.x;
    int lane = tid & 31;
    int warp = tid >> 5;
    int rowBase = blockIdx.y * 128;
    int colBase = blockIdx.x * 128;
    int warpM = (warp >> 2) * 64;
    int warpN = (warp & 3) * 32;

    int r0 = tid >> 2, c0 = (tid & 3) * 8;
    const __nv_bfloat16* Ap0 = A2 + (size_t)(rowBase + r0) * lda + c0;
    const __nv_bfloat16* Ap1 = A2 + (size_t)(rowBase + r0 + 64) * lda + c0;
    const __nv_bfloat16* Wp0 = W2 + (size_t)(colBase + r0) * K2 + c0;
    const __nv_bfloat16* Wp1 = W2 + (size_t)(colBase + r0 + 64) * K2 + c0;

    unsigned sA = (unsigned)__cvta_generic_to_shared(Asm);
    unsigned sW = (unsigned)__cvta_generic_to_shared(Wsm);
    unsigned stA0 = sA + (r0 * SKS + c0) * 2;
    unsigned stA1 = sA + ((r0 + 64) * SKS + c0) * 2;
    unsigned stW0 = sW + (r0 * SKS + c0) * 2;
    unsigned stW1 = sW + ((r0 + 64) * SKS + c0) * 2;

    float acc[4][4][4];
    #pragma unroll
    for (int i = 0; i < 4; i++)
        #pragma unroll
        for (int j = 0; j < 4; j++)
            #pragma unroll
            for (int q = 0; q < 4; q++) acc[i][j][q] = 0.f;

    int l16 = lane & 15;
    unsigned aAddrBase = sA + ((warpM + l16) * SKS + (lane >> 4) * 8) * 2;
    unsigned wAddrBase = sW + ((warpN + (l16 & 7)) * SKS + ((l16 >> 3) & 1) * 8) * 2;

    int nIter = K2 >> 5;

    cpa16(stA0, Ap0); cpa16(stA1, Ap1);
    cpa16(stW0, Wp0); cpa16(stW1, Wp1);
    cpa_commit();
    {
        unsigned off = TILEB;
        cpa16(stA0 + off, Ap0 + 32); cpa16(stA1 + off, Ap1 + 32);
        cpa16(stW0 + off, Wp0 + 32); cpa16(stW1 + off, Wp1 + 32);
        cpa_commit();
    }

    int bufc = 0, bufn = 2;
    for (int it = 0; it < nIter; it++) {
        if (it + 1 < nIter) cpa_wait<1>(); else cpa_wait<0>();
        __syncthreads();
        if (it + 2 < nIter) {
            int ko = (it + 2) << 5;
            unsigned off = bufn * TILEB;
            cpa16(stA0 + off, Ap0 + ko); cpa16(stA1 + off, Ap1 + ko);
            cpa16(stW0 + off, Wp0 + ko); cpa16(stW1 + off, Wp1 + ko);
            cpa_commit();
        }

        unsigned aB = aAddrBase + bufc * TILEB;
        unsigned wB = wAddrBase + bufc * TILEB;
        #pragma unroll
        for (int kk = 0; kk < 32; kk += 16) {
            unsigned b[4][2];
            #pragma unroll
            for (int j = 0; j < 4; j++)
                ldsmx2(b[j], wB + (j * 8 * SKS + kk) * 2);
            #pragma unroll
            for (int i = 0; i < 4; i++) {
                unsigned a[4];
                ldsmx4(a, aB + (i * 16 * SKS + kk) * 2);
                #pragma unroll
                for (int j = 0; j < 4; j++)
                    mma16816(acc[i][j], a, b[j]);
            }
        }
        bufc = (bufc + 1 == STAGES) ? 0 : bufc + 1;
        bufn = (bufn + 1 == STAGES) ? 0 : bufn + 1;
    }

    int erow = lane >> 2;
    int ecol = (lane & 3) * 2;
    #pragma unroll
    for (int i = 0; i < 4; i++) {
        int row = rowBase + warpM + i * 16 + erow;
        #pragma unroll
        for (int j = 0; j < 4; j++) {
            int col = colBase + warpN + j * 8 + ecol;
            float v0 = acc[i][j][0], v1 = acc[i][j][1];
            float v2 = acc[i][j][2], v3 = acc[i][j][3];
            if (EPI == 1) {
                float b0 = bias[col], b1 = bias[col + 1];
                v0 += b0; v1 += b1; v2 += b0; v3 += b1;
            }
            if (EPI == 3) {
                v0 += R[(size_t)row * ldr + col];
                v1 += R[(size_t)row * ldr + col + 1];
                v2 += R[(size_t)(row + 8) * ldr + col];
                v3 += R[(size_t)(row + 8) * ldr + col + 1];
                split_store2(C3, row,     dirOff + col, v0, v1);
                split_store2(C3, row + 8, dirOff + col, v2, v3);
            } else {
                C[(size_t)row * ldc + col]           = v0;
                C[(size_t)row * ldc + col + 1]       = v1;
                C[(size_t)(row + 8) * ldc + col]     = v2;
                C[(size_t)(row + 8) * ldc + col + 1] = v3;
            }
        }
    }
}

// ---------------- BN=64 variant (for N=384 GEMMs): BM=128, BN=64 ----------------
// 8 warps arranged 4(M) x 2(N); warp tile 32x32. Grid (N/64, M/128).
#define ATILEB (128 * SKS * 2)
#define WTILEB (64 * SKS * 2)
template<int EPI>
__global__ __launch_bounds__(256, 2) void bgemm64(
    const __nv_bfloat16* __restrict__ A2, int lda,
    const __nv_bfloat16* __restrict__ W2, int K2,
    const float* __restrict__ bias,
    const float* __restrict__ R, int ldr,
    float* __restrict__ C, int ldc,
    __nv_bfloat16* __restrict__ C3, int dirOff)
{
    extern __shared__ __nv_bfloat16 dsm[];
    __nv_bfloat16* Asm = dsm;                         // STAGES x 128 x SKS
    __nv_bfloat16* Wsm = dsm + STAGES * 128 * SKS;    // STAGES x 64 x SKS

    int tid = threadIdx.x;
    int lane = tid & 31;
    int warp = tid >> 5;
    int rowBase = blockIdx.y * 128;
    int colBase = blockIdx.x * 64;
    int warpM = (warp >> 1) * 32;
    int warpN = (warp & 1) * 32;

    int r0 = tid >> 2, c0 = (tid & 3) * 8;
    const __nv_bfloat16* Ap0 = A2 + (size_t)(rowBase + r0) * lda + c0;
    const __nv_bfloat16* Ap1 = A2 + (size_t)(rowBase + r0 + 64) * lda + c0;
    const __nv_bfloat16* Wp0 = W2 + (size_t)(colBase + r0) * K2 + c0;   // r0<64 only

    unsigned sA = (unsigned)__cvta_generic_to_shared(Asm);
    unsigned sW = (unsigned)__cvta_generic_to_shared(Wsm);
    unsigned stA0 = sA + (r0 * SKS + c0) * 2;
    unsigned stA1 = sA + ((r0 + 64) * SKS + c0) * 2;
    unsigned stW0 = sW + (r0 * SKS + c0) * 2;
    bool wload = (r0 < 64);

    float acc[2][4][4];
    #pragma unroll
    for (int i = 0; i < 2; i++)
        #pragma unroll
        for (int j = 0; j < 4; j++)
            #pragma unroll
            for (int q = 0; q < 4; q++) acc[i][j][q] = 0.f;

    int l16 = lane & 15;
    unsigned aAddrBase = sA + ((warpM + l16) * SKS + (lane >> 4) * 8) * 2;
    unsigned wAddrBase = sW + ((warpN + (l16 & 7)) * SKS + ((l16 >> 3) & 1) * 8) * 2;

    int nIter = K2 >> 5;

    cpa16(stA0, Ap0); cpa16(stA1, Ap1);
    if (wload) cpa16(stW0, Wp0);
    cpa_commit();
    {
        cpa16(stA0 + ATILEB, Ap0 + 32); cpa16(stA1 + ATILEB, Ap1 + 32);
        if (wload) cpa16(stW0 + WTILEB, Wp0 + 32);
        cpa_commit();
    }

    int bufc = 0, bufn = 2;
    for (int it = 0; it < nIter; it++) {
        if (it + 1 < nIter) cpa_wait<1>(); else cpa_wait<0>();
        __syncthreads();
        if (it + 2 < nIter) {
            int ko = (it + 2) << 5;
            cpa16(stA0 + bufn * ATILEB, Ap0 + ko);
            cpa16(stA1 + bufn * ATILEB, Ap1 + ko);
            if (wload) cpa16(stW0 + bufn * WTILEB, Wp0 + ko);
            cpa_commit();
        }

        unsigned aB = aAddrBase + bufc * ATILEB;
        unsigned wB = wAddrBase + bufc * WTILEB;
        #pragma unroll
        for (int kk = 0; kk < 32; kk += 16) {
            unsigned b[4][2];
            #pragma unroll
            for (int j = 0; j < 4; j++)
                ldsmx2(b[j], wB + (j * 8 * SKS + kk) * 2);
            #pragma unroll
            for (int i = 0; i < 2; i++) {
                unsigned a[4];
                ldsmx4(a, aB + (i * 16 * SKS + kk) * 2);
                #pragma unroll
                for (int j = 0; j < 4; j++)
                    mma16816(acc[i][j], a, b[j]);
            }
        }
        bufc = (bufc + 1 == STAGES) ? 0 : bufc + 1;
        bufn = (bufn + 1 == STAGES) ? 0 : bufn + 1;
    }

    int erow = lane >> 2;
    int ecol = (lane & 3) * 2;
    #pragma unroll
    for (int i = 0; i < 2; i++) {
        int row = rowBase + warpM + i * 16 + erow;
        #pragma unroll
        for (int j = 0; j < 4; j++) {
            int col = colBase + warpN + j * 8 + ecol;
            float v0 = acc[i][j][0], v1 = acc[i][j][1];
            float v2 = acc[i][j][2], v3 = acc[i][j][3];
            if (EPI == 1) {
                float b0 = bias[col], b1 = bias[col + 1];
                v0 += b0; v1 += b1; v2 += b0; v3 += b1;
            }
            if (EPI == 3) {
                v0 += R[(size_t)row * ldr + col];
                v1 += R[(size_t)row * ldr + col + 1];
                v2 += R[(size_t)(row + 8) * ldr + col];
                v3 += R[(size_t)(row + 8) * ldr + col + 1];
                split_store2(C3, row,     dirOff + col, v0, v1);
                split_store2(C3, row + 8, dirOff + col, v2, v3);
            } else {
                C[(size_t)row * ldc + col]           = v0;
                C[(size_t)row * ldc + col + 1]       = v1;
                C[(size_t)(row + 8) * ldc + col]     = v2;
                C[(size_t)(row + 8) * ldc + col + 1] = v3;
            }
        }
    }
}

// ---------------- fp32 SGEMM (dt GEMM, K=24) ----------------
template<int EPI>
__global__ __launch_bounds__(256) void sgemm128(
    const float* __restrict__ A, int lda,
    const float* __restrict__ W, int K,
    const float* __restrict__ bias,
    float* __restrict__ C, int ldc)
{
    __shared__ float As[8][128];
    __shared__ float Ws[8][128];
    int tid = threadIdx.x;
    int rowBase = blockIdx.y * 128;
    int colBase = blockIdx.x * 128;
    int ty = tid >> 4, tx = tid & 15;
    int arow = tid >> 1;
    int ak   = (tid & 1) * 4;

    float acc[8][8];
    #pragma unroll
    for (int i = 0; i < 8; i++)
        #pragma unroll
        for (int j = 0; j < 8; j++) acc[i][j] = 0.f;

    const float* Aptr = A + (size_t)(rowBase + arow) * lda + ak;
    const float* Wptr = W + (size_t)(colBase + arow) * K + ak;

    for (int k0 = 0; k0 < K; k0 += 8) {
        float4 av = *(const float4*)(Aptr + k0);
        float4 wv = *(const float4*)(Wptr + k0);
        __syncthreads();
        As[ak+0][arow] = av.x; As[ak+1][arow] = av.y;
        As[ak+2][arow] = av.z; As[ak+3][arow] = av.w;
        Ws[ak+0][arow] = wv.x; Ws[ak+1][arow] = wv.y;
        Ws[ak+2][arow] = wv.z; Ws[ak+3][arow] = wv.w;
        __syncthreads();
        #pragma unroll
        for (int k = 0; k < 8; k++) {
            float a[8], w[8];
            *(float4*)&a[0] = *(const float4*)&As[k][ty*8];
            *(float4*)&a[4] = *(const float4*)&As[k][ty*8+4];
            *(float4*)&w[0] = *(const float4*)&Ws[k][tx*8];
            *(float4*)&w[4] = *(const float4*)&Ws[k][tx*8+4];
            #pragma unroll
            for (int i = 0; i < 8; i++)
                #pragma unroll
                for (int j = 0; j < 8; j++)
                    acc[i][j] = fmaf(a[i], w[j], acc[i][j]);
        }
    }
    #pragma unroll
    for (int i = 0; i < 8; i++) {
        int row = rowBase + ty * 8 + i;
        #pragma unroll
        for (int j = 0; j < 8; j++) {
            int col = colBase + tx * 8 + j;
            float v = acc[i][j];
            if (EPI == 2) {
                v += bias[col];
                v = (v > 20.f) ? v : log1pf(__expf(v));
            }
            C[(size_t)row * ldc + col] = v;
        }
    }
}

// ---------------- small-N GEMM (x_proj: N=56, K=768) ----------------
__global__ __launch_bounds__(256) void sgemm_s(
    const float* __restrict__ A, int lda,
    const float* __restrict__ W, int K,
    float* __restrict__ C, int ldc, int N)
{
    __shared__ float As[16][32];
    __shared__ float Ws[16][64];
    int tid = threadIdx.x;
    int rowBase = blockIdx.y * 32;
    int colBase = blockIdx.x * 64;
    int ty = tid >> 4, tx = tid & 15;
    float acc[2][4] = {{0.f,0.f,0.f,0.f},{0.f,0.f,0.f,0.f}};
    int wn = tid >> 2, wk = (tid & 3) * 4;
    bool wv = (colBase + wn) < N;

    for (int k0 = 0; k0 < K; k0 += 16) {
        __syncthreads();
        #pragma unroll
        for (int i = tid; i < 512; i += 256) {
            int r = i >> 4, k = i & 15;
            As[k][r] = A[(size_t)(rowBase + r) * lda + k0 + k];
        }
        float4 wvv = wv ? *(const float4*)&W[(size_t)(colBase + wn) * K + k0 + wk]
                        : make_float4(0.f,0.f,0.f,0.f);
        Ws[wk+0][wn] = wvv.x; Ws[wk+1][wn] = wvv.y;
        Ws[wk+2][wn] = wvv.z; Ws[wk+3][wn] = wvv.w;
        __syncthreads();
        #pragma unroll
        for (int k = 0; k < 16; k++) {
            float a0 = As[k][ty], a1 = As[k][ty + 16];
            float4 w4 = *(const float4*)&Ws[k][tx*4];
            acc[0][0] = fmaf(a0, w4.x, acc[0][0]);
            acc[0][1] = fmaf(a0, w4.y, acc[0][1]);
            acc[0][2] = fmaf(a0, w4.z, acc[0][2]);
            acc[0][3] = fmaf(a0, w4.w, acc[0][3]);
            acc[1][0] = fmaf(a1, w4.x, acc[1][0]);
            acc[1][1] = fmaf(a1, w4.y, acc[1][1]);
            acc[1][2] = fmaf(a1, w4.z, acc[1][2]);
            acc[1][3] = fmaf(a1, w4.w, acc[1][3]);
        }
    }
    #pragma unroll
    for (int i = 0; i < 2; i++) {
        int row = rowBase + ty + i * 16;
        #pragma unroll
        for (int j = 0; j < 4; j++) {
            int col = colBase + tx * 4 + j;
            if (col < N) C[(size_t)row * ldc + col] = acc[i][j];
        }
    }
}

// ---------------- causal depthwise conv (k=4) + SiLU ----------------
__global__ void conv_kernel(const float* __restrict__ XZ,
                            const float* __restrict__ Wc,
                            const float* __restrict__ Bc,
                            float* __restrict__ XC, int dir)
{
    int idx = blockIdx.x * blockDim.x + threadIdx.x;
    if (idx >= ROWS * DI) return;
    int d = idx % DI;
    int t = (idx / DI) % LSEQ;
    int b = idx / (DI * LSEQ);
    const float* xm = XZ + (size_t)b * LSEQ * (2 * DI) + d;
    float acc = Bc[d];
    #pragma unroll
    for (int j = 0; j < 4; j++) {
        int tt = (dir == 0) ? (t - 3 + j) : (t + 3 - j);
        if (tt >= 0 && tt < LSEQ)
            acc = fmaf(Wc[d * 4 + j], xm[(size_t)tt * (2 * DI)], acc);
    }
    acc = acc / (1.f + __expf(-acc));
    XC[idx] = acc;
}

// ---------------- selective scan, fused gate + bf16 split output ----------------
__global__ __launch_bounds__(128) void scan_kernel(
    const float* __restrict__ XC,
    const float* __restrict__ DT,
    const float* __restrict__ XDBL,
    const float* __restrict__ XZ,
    const float* __restrict__ Alog,
    const float* __restrict__ Dp,
    __nv_bfloat16* __restrict__ A3, int dir)
{
    __shared__ float Bs[LSEQ][DS];
    __shared__ float Cs[LSEQ][DS];
    int b = blockIdx.x;
    int d = blockIdx.y * 128 + threadIdx.x;

    const float* xd = XDBL + (size_t)b * LSEQ * XPD;
    for (int i = threadIdx.x; i < LSEQ * DS; i += 128) {
        int t = i / DS, n = i % DS;
        Bs[t][n] = xd[t * XPD + DTRK + n];
        Cs[t][n] = xd[t * XPD + DTRK + DS + n];
    }
    __syncthreads();

    float A[DS];
    #pragma unroll
    for (int n = 0; n < DS; n++) A[n] = -__expf(Alog[d * DS + n]);
    float Dd = Dp[d];
    float h[DS];
    #pragma unroll
    for (int n = 0; n < DS; n++) h[n] = 0.f;

    const float* ub  = XC + (size_t)b * LSEQ * DI + d;
    const float* dtb = DT + (size_t)b * LSEQ * DI + d;
    const float* zb  = XZ + (size_t)b * LSEQ * (2 * DI) + DI + d;

    for (int s = 0; s < LSEQ; s++) {
        int t = dir ? (LSEQ - 1 - s) : s;
        float dtv = dtb[(size_t)t * DI];
        float u   = ub[(size_t)t * DI];
        float du  = dtv * u;
        float accv = 0.f;
        #pragma unroll
        for (int n = 0; n < DS; n++) {
            float dA = __expf(dtv * A[n]);
            h[n] = fmaf(dA, h[n], du * Bs[t][n]);
            accv = fmaf(h[n], Cs[t][n], accv);
        }
        float z = zb[(size_t)t * (2 * DI)];
        float sz = z / (1.f + __expf(-z));
        float y = (accv + u * Dd) * sz;
        __nv_bfloat16 hi = __float2bfloat16(y);
        __nv_bfloat16 lo = __float2bfloat16(y - __bfloat162float(hi));
        size_t rb = ((size_t)b * LSEQ + t) * (3 * DI);
        A3[rb + d]          = hi;
        A3[rb + DI + d]     = hi;
        A3[rb + 2 * DI + d] = lo;
    }
}

// ---------------- final scatter ----------------
__global__ void final_kernel(const float* __restrict__ X,
                             const float* __restrict__ FUSED,
                             const int* __restrict__ inv_idx,
                             float* __restrict__ OUT)
{
    int idx = blockIdx.x * blockDim.x + threadIdx.x;
    if (idx >= NB * SEQF * DM) return;
    int c = idx % DM;
    int s = (idx / DM) % SEQF;
    int b = idx / (DM * SEQF);
    if (s == 0) {
        OUT[idx] = X[idx];
    } else {
        int src = inv_idx[s - 1];
        OUT[idx] = FUSED[((size_t)b * LSEQ + src) * DM + c];
    }
}

// ---------------- host launch ----------------
extern "C" void kernel_launch(void* const* d_in, const int* in_sizes, int n_in,
                              void* d_out, int out_size)
{
    float* S = nullptr;
    cudaGetSymbolAddress((void**)&S, g_scratch);

    float* pr    = S + OFF_PR;
    float* xz    = S + OFF_XZ;
    float* xc    = S + OFF_XC;
    float* xdbl  = S + OFF_XDBL;
    float* dtb   = S + OFF_DT;
    float* fused = S + OFF_FUSED;
    __nv_bfloat16* a3   = (__nv_bfloat16*)(S + OFF_ACT3);
    __nv_bfloat16* cat3 = (__nv_bfloat16*)(S + OFF_CAT3);
    __nv_bfloat16* w3   = (__nv_bfloat16*)(S + OFF_W3);

    const int SMEM_BG  = STAGES * 128 * SKS * 2 * 2;          // 61440
    const int SMEM_BG64 = STAGES * (128 + 64) * SKS * 2;      // 46080
    cudaFuncSetAttribute(bgemm<0>,  cudaFuncAttributeMaxDynamicSharedMemorySize, SMEM_BG);
    cudaFuncSetAttribute(bgemm64<1>, cudaFuncAttributeMaxDynamicSharedMemorySize, SMEM_BG64);
    cudaFuncSetAttribute(bgemm64<3>, cudaFuncAttributeMaxDynamicSharedMemorySize, SMEM_BG64);

    const float* x        = (const float*)d_in[0];
    const float* fusion_w = (const float*)d_in[23];
    const float* fusion_b = (const float*)d_in[24];
    const int*   scan_idx = (const int*)d_in[25];
    const int*   inv_idx  = (const int*)d_in[26];

    gather_kernel<<<(ROWS*DM + 255)/256, 256>>>(x, scan_idx, pr);

    for (int dir = 0; dir < 2; dir++) {
        int base = 1 + dir * 11;
        const float* ln_g   = (const float*)d_in[base + 0];
        const float* ln_b   = (const float*)d_in[base + 1];
        const float* in_w   = (const float*)d_in[base + 2];   // (1536,384)
        const float* conv_w = (const float*)d_in[base + 3];
        const float* conv_b = (const float*)d_in[base + 4];
        const float* x_w    = (const float*)d_in[base + 5];   // (56,768)
        const float* dt_w   = (const float*)d_in[base + 6];   // (768,24)
        const float* dt_b   = (const float*)d_in[base + 7];
        const float* A_log  = (const float*)d_in[base + 8];
        const float* Dp     = (const float*)d_in[base + 9];
        const float* out_w  = (const float*)d_in[base + 10];  // (384,768)

        ln_split_kernel<<<ROWS, 128>>>(pr, ln_g, ln_b, a3);

        // in_proj: xz = xln @ in_w^T  (K'=1152, N=1536)
        split3_wt<<<(2*DI*DM + 255)/256, 256>>>(in_w, w3, 2*DI*DM, DM);
        bgemm<0><<<dim3(12, 48), 256, SMEM_BG>>>(a3, 3*DM, w3, 3*DM,
                                                 nullptr, nullptr, 0, xz, 2*DI,
                                                 nullptr, 0);

        conv_kernel<<<(ROWS*DI + 255)/256, 256>>>(xz, conv_w, conv_b, xc, dir);

        sgemm_s<<<dim3(1, ROWS/32), 256>>>(xc, DI, x_w, DI, xdbl, XPD, XPD);

        sgemm128<2><<<dim3(6, 48), 256>>>(xdbl, XPD, dt_w, DTRK, dt_b, dtb, DI);

        scan_kernel<<<dim3(NB, 6), 128>>>(xc, dtb, xdbl, xz, A_log, Dp, a3, dir);

        // out_proj: cat3[:, dir cols] = split(y @ out_w^T + pr)  (K'=2304, N=384)
        split3_wt<<<(DM*DI + 255)/256, 256>>>(out_w, w3, DM*DI, DI);
        bgemm64<3><<<dim3(6, 48), 256, SMEM_BG64>>>(a3, 3*DI, w3, 3*DI,
                                                    nullptr, pr, DM, nullptr, 0,
                                                    cat3, dir * DM);
    }

    // fusion: fused = cat @ fusion_w^T + fusion_b  (K'=2304, N=384)
    split3_wt<<<(DM*DI + 255)/256, 256>>>(fusion_w, w3, DM*DI, DI);
    bgemm64<1><<<dim3(6, 48), 256, SMEM_BG64>>>(cat3, 2304, w3, 3*(2*DM),
                                                fusion_b, nullptr, 0, fused, DM,
                                                nullptr, 0);

    final_kernel<<<(NB*SEQF*DM + 255)/256, 256>>>(x, fused, inv_idx, (float*)d_out);
}

// round 11
// speedup vs baseline: 1.0712x; 1.0712x over previous
#include <cuda_runtime.h>
#include <cuda_bf16.h>
#include <math.h>

// ---------------- problem constants ----------------
#define NB    32
#define LSEQ  192
#define SEQF  193
#define DM    384
#define DI    768
#define DS    16
#define DTRK  24
#define XPD   56
#define ROWS  (NB*LSEQ)   // 6144

// ---------------- scratch (floats) ----------------
__device__ float g_scratch[43696128];

#define OFF_PR     0
#define OFF_XZ     2359296
#define OFF_XC     11796480
#define OFF_XDBL   16515072
#define OFF_DT     16859136
#define OFF_FUSED  21577728
#define OFF_ACT3   23937024
#define OFF_CAT3   31014912
#define OFF_W3     38092800

// ---------------- gather ----------------
__global__ void gather_kernel(const float* __restrict__ X,
                              const int* __restrict__ scan_idx,
                              float* __restrict__ PR)
{
    int idx = blockIdx.x * blockDim.x + threadIdx.x;
    if (idx >= ROWS * DM) return;
    int c = idx % DM;
    int t = (idx / DM) % LSEQ;
    int b = idx / (DM * LSEQ);
    int src = scan_idx[t];
    PR[idx] = X[((size_t)b * SEQF + 1 + src) * DM + c];
}

// ---------------- layernorm fused with 3-block bf16 split ----------------
__global__ __launch_bounds__(128) void ln_split_kernel(
    const float* __restrict__ X,
    const float* __restrict__ G,
    const float* __restrict__ Bb,
    __nv_bfloat16* __restrict__ A3)
{
    int row = blockIdx.x;
    const float* x = X + (size_t)row * DM;
    float v[3]; float s = 0.f, ss = 0.f;
    #pragma unroll
    for (int i = 0; i < 3; i++) {
        v[i] = x[threadIdx.x + i * 128];
        s += v[i]; ss += v[i] * v[i];
    }
    __shared__ float sh_s[4], sh_ss[4];
    #pragma unroll
    for (int o = 16; o; o >>= 1) {
        s  += __shfl_down_sync(0xffffffffu, s,  o);
        ss += __shfl_down_sync(0xffffffffu, ss, o);
    }
    int wid = threadIdx.x >> 5, lid = threadIdx.x & 31;
    if (lid == 0) { sh_s[wid] = s; sh_ss[wid] = ss; }
    __syncthreads();
    float ts = sh_s[0] + sh_s[1] + sh_s[2] + sh_s[3];
    float tss = sh_ss[0] + sh_ss[1] + sh_ss[2] + sh_ss[3];
    float mean = ts * (1.f / DM);
    float var = tss * (1.f / DM) - mean * mean;
    float rstd = rsqrtf(var + 1e-5f);
    __nv_bfloat16* a = A3 + (size_t)row * (3 * DM);
    #pragma unroll
    for (int i = 0; i < 3; i++) {
        int c = threadIdx.x + i * 128;
        float y = (v[i] - mean) * rstd * G[c] + Bb[c];
        __nv_bfloat16 hi = __float2bfloat16(y);
        __nv_bfloat16 lo = __float2bfloat16(y - __bfloat162float(hi));
        a[c]          = hi;
        a[DM + c]     = hi;
        a[2 * DM + c] = lo;
    }
}

// ---------------- weight 3-block split: Y[n, 3K] = [hi | lo | hi] ----------------
__global__ void split3_wt(const float* __restrict__ X,
                          __nv_bfloat16* __restrict__ Y,
                          int total, int K)
{
    int idx = blockIdx.x * blockDim.x + threadIdx.x;
    if (idx >= total) return;
    int m = idx / K, k = idx % K;
    float x = X[idx];
    __nv_bfloat16 hi = __float2bfloat16(x);
    __nv_bfloat16 lo = __float2bfloat16(x - __bfloat162float(hi));
    size_t r = (size_t)m * (3 * K);
    Y[r + k]         = hi;
    Y[r + K + k]     = lo;
    Y[r + 2 * K + k] = hi;
}

// ---------------- mma / cp.async helpers ----------------
__device__ __forceinline__ void mma16816(float* c, const unsigned* a, const unsigned* b)
{
    asm volatile(
        "mma.sync.aligned.m16n8k16.row.col.f32.bf16.bf16.f32 "
        "{%0,%1,%2,%3}, {%4,%5,%6,%7}, {%8,%9}, {%0,%1,%2,%3};\n"
        : "+f"(c[0]), "+f"(c[1]), "+f"(c[2]), "+f"(c[3])
        : "r"(a[0]), "r"(a[1]), "r"(a[2]), "r"(a[3]), "r"(b[0]), "r"(b[1]));
}
__device__ __forceinline__ void ldsmx4(unsigned* r, unsigned addr)
{
    asm volatile("ldmatrix.sync.aligned.m8n8.x4.shared.b16 {%0,%1,%2,%3}, [%4];"
                 : "=r"(r[0]), "=r"(r[1]), "=r"(r[2]), "=r"(r[3]) : "r"(addr));
}
__device__ __forceinline__ void ldsmx2(unsigned* r, unsigned addr)
{
    asm volatile("ldmatrix.sync.aligned.m8n8.x2.shared.b16 {%0,%1}, [%2];"
                 : "=r"(r[0]), "=r"(r[1]) : "r"(addr));
}
__device__ __forceinline__ void cpa16(unsigned dst, const void* src)
{
    asm volatile("cp.async.cg.shared.global [%0], [%1], 16;\n" :: "r"(dst), "l"(src));
}
__device__ __forceinline__ void cpa_commit()
{
    asm volatile("cp.async.commit_group;\n");
}
template<int N>
__device__ __forceinline__ void cpa_wait()
{
    asm volatile("cp.async.wait_group %0;\n" :: "n"(N));
}

// split-bf16 store for out_proj epilogue (cat3 row = 2304 bf16: [hi|hi|lo])
__device__ __forceinline__ void split_store2(__nv_bfloat16* C3, int row, int colL,
                                             float s0, float s1)
{
    __nv_bfloat16 h0 = __float2bfloat16(s0);
    __nv_bfloat16 h1 = __float2bfloat16(s1);
    __nv_bfloat16 l0 = __float2bfloat16(s0 - __bfloat162float(h0));
    __nv_bfloat16 l1 = __float2bfloat16(s1 - __bfloat162float(h1));
    __nv_bfloat162 hp; hp.x = h0; hp.y = h1;
    __nv_bfloat162 lp; lp.x = l0; lp.y = l1;
    size_t rb = (size_t)row * 2304;
    *(__nv_bfloat162*)&C3[rb + colL]        = hp;
    *(__nv_bfloat162*)&C3[rb + 768 + colL]  = hp;
    *(__nv_bfloat162*)&C3[rb + 1536 + colL] = lp;
}

// ---------------- 3-stage pipelined bf16 tensor GEMM, BN=128 ----------------
// EPI: 0 none (fp32 C), 1 +bias (fp32 C), 3 +residual then split-bf16 store to C3
#define SKS 40
#define TILEB (128 * SKS * 2)
#define STAGES 3
template<int EPI>
__global__ __launch_bounds__(256, 2) void bgemm(
    const __nv_bfloat16* __restrict__ A2, int lda,
    const __nv_bfloat16* __restrict__ W2, int K2,
    const float* __restrict__ bias,
    const float* __restrict__ R, int ldr,
    float* __restrict__ C, int ldc,
    __nv_bfloat16* __restrict__ C3, int dirOff)
{
    extern __shared__ __nv_bfloat16 dsm[];
    __nv_bfloat16* Asm = dsm;
    __nv_bfloat16* Wsm = dsm + STAGES * 128 * SKS;

    int tid = threadIdx.x;
    int lane = tid & 31;
    int warp = tid >> 5;
    int rowBase = blockIdx.y * 128;
    int colBase = blockIdx.x * 128;
    int warpM = (warp >> 2) * 64;
    int warpN = (warp & 3) * 32;

    int r0 = tid >> 2, c0 = (tid & 3) * 8;
    const __nv_bfloat16* Ap0 = A2 + (size_t)(rowBase + r0) * lda + c0;
    const __nv_bfloat16* Ap1 = A2 + (size_t)(rowBase + r0 + 64) * lda + c0;
    const __nv_bfloat16* Wp0 = W2 + (size_t)(colBase + r0) * K2 + c0;
    const __nv_bfloat16* Wp1 = W2 + (size_t)(colBase + r0 + 64) * K2 + c0;

    unsigned sA = (unsigned)__cvta_generic_to_shared(Asm);
    unsigned sW = (unsigned)__cvta_generic_to_shared(Wsm);
    unsigned stA0 = sA + (r0 * SKS + c0) * 2;
    unsigned stA1 = sA + ((r0 + 64) * SKS + c0) * 2;
    unsigned stW0 = sW + (r0 * SKS + c0) * 2;
    unsigned stW1 = sW + ((r0 + 64) * SKS + c0) * 2;

    float acc[4][4][4];
    #pragma unroll
    for (int i = 0; i < 4; i++)
        #pragma unroll
        for (int j = 0; j < 4; j++)
            #pragma unroll
            for (int q = 0; q < 4; q++) acc[i][j][q] = 0.f;

    int l16 = lane & 15;
    unsigned aAddrBase = sA + ((warpM + l16) * SKS + (lane >> 4) * 8) * 2;
    unsigned wAddrBase = sW + ((warpN + (l16 & 7)) * SKS + ((l16 >> 3) & 1) * 8) * 2;

    int nIter = K2 >> 5;

    cpa16(stA0, Ap0); cpa16(stA1, Ap1);
    cpa16(stW0, Wp0); cpa16(stW1, Wp1);
    cpa_commit();
    {
        unsigned off = TILEB;
        cpa16(stA0 + off, Ap0 + 32); cpa16(stA1 + off, Ap1 + 32);
        cpa16(stW0 + off, Wp0 + 32); cpa16(stW1 + off, Wp1 + 32);
        cpa_commit();
    }

    int bufc = 0, bufn = 2;
    for (int it = 0; it < nIter; it++) {
        if (it + 1 < nIter) cpa_wait<1>(); else cpa_wait<0>();
        __syncthreads();
        if (it + 2 < nIter) {
            int ko = (it + 2) << 5;
            unsigned off = bufn * TILEB;
            cpa16(stA0 + off, Ap0 + ko); cpa16(stA1 + off, Ap1 + ko);
            cpa16(stW0 + off, Wp0 + ko); cpa16(stW1 + off, Wp1 + ko);
            cpa_commit();
        }

        unsigned aB = aAddrBase + bufc * TILEB;
        unsigned wB = wAddrBase + bufc * TILEB;
        #pragma unroll
        for (int kk = 0; kk < 32; kk += 16) {
            unsigned b[4][2];
            #pragma unroll
            for (int j = 0; j < 4; j++)
                ldsmx2(b[j], wB + (j * 8 * SKS + kk) * 2);
            #pragma unroll
            for (int i = 0; i < 4; i++) {
                unsigned a[4];
                ldsmx4(a, aB + (i * 16 * SKS + kk) * 2);
                #pragma unroll
                for (int j = 0; j < 4; j++)
                    mma16816(acc[i][j], a, b[j]);
            }
        }
        bufc = (bufc + 1 == STAGES) ? 0 : bufc + 1;
        bufn = (bufn + 1 == STAGES) ? 0 : bufn + 1;
    }

    int erow = lane >> 2;
    int ecol = (lane & 3) * 2;
    #pragma unroll
    for (int i = 0; i < 4; i++) {
        int row = rowBase + warpM + i * 16 + erow;
        #pragma unroll
        for (int j = 0; j < 4; j++) {
            int col = colBase + warpN + j * 8 + ecol;
            float v0 = acc[i][j][0], v1 = acc[i][j][1];
            float v2 = acc[i][j][2], v3 = acc[i][j][3];
            if (EPI == 1) {
                float b0 = bias[col], b1 = bias[col + 1];
                v0 += b0; v1 += b1; v2 += b0; v3 += b1;
            }
            if (EPI == 3) {
                v0 += R[(size_t)row * ldr + col];
                v1 += R[(size_t)row * ldr + col + 1];
                v2 += R[(size_t)(row + 8) * ldr + col];
                v3 += R[(size_t)(row + 8) * ldr + col + 1];
                split_store2(C3, row,     dirOff + col, v0, v1);
                split_store2(C3, row + 8, dirOff + col, v2, v3);
            } else {
                C[(size_t)row * ldc + col]           = v0;
                C[(size_t)row * ldc + col + 1]       = v1;
                C[(size_t)(row + 8) * ldc + col]     = v2;
                C[(size_t)(row + 8) * ldc + col + 1] = v3;
            }
        }
    }
}

// ---------------- fp32 SGEMM (dt GEMM, K=24) ----------------
template<int EPI>
__global__ __launch_bounds__(256) void sgemm128(
    const float* __restrict__ A, int lda,
    const float* __restrict__ W, int K,
    const float* __restrict__ bias,
    float* __restrict__ C, int ldc)
{
    __shared__ float As[8][128];
    __shared__ float Ws[8][128];
    int tid = threadIdx.x;
    int rowBase = blockIdx.y * 128;
    int colBase = blockIdx.x * 128;
    int ty = tid >> 4, tx = tid & 15;
    int arow = tid >> 1;
    int ak   = (tid & 1) * 4;

    float acc[8][8];
    #pragma unroll
    for (int i = 0; i < 8; i++)
        #pragma unroll
        for (int j = 0; j < 8; j++) acc[i][j] = 0.f;

    const float* Aptr = A + (size_t)(rowBase + arow) * lda + ak;
    const float* Wptr = W + (size_t)(colBase + arow) * K + ak;

    for (int k0 = 0; k0 < K; k0 += 8) {
        float4 av = *(const float4*)(Aptr + k0);
        float4 wv = *(const float4*)(Wptr + k0);
        __syncthreads();
        As[ak+0][arow] = av.x; As[ak+1][arow] = av.y;
        As[ak+2][arow] = av.z; As[ak+3][arow] = av.w;
        Ws[ak+0][arow] = wv.x; Ws[ak+1][arow] = wv.y;
        Ws[ak+2][arow] = wv.z; Ws[ak+3][arow] = wv.w;
        __syncthreads();
        #pragma unroll
        for (int k = 0; k < 8; k++) {
            float a[8], w[8];
            *(float4*)&a[0] = *(const float4*)&As[k][ty*8];
            *(float4*)&a[4] = *(const float4*)&As[k][ty*8+4];
            *(float4*)&w[0] = *(const float4*)&Ws[k][tx*8];
            *(float4*)&w[4] = *(const float4*)&Ws[k][tx*8+4];
            #pragma unroll
            for (int i = 0; i < 8; i++)
                #pragma unroll
                for (int j = 0; j < 8; j++)
                    acc[i][j] = fmaf(a[i], w[j], acc[i][j]);
        }
    }
    #pragma unroll
    for (int i = 0; i < 8; i++) {
        int row = rowBase + ty * 8 + i;
        #pragma unroll
        for (int j = 0; j < 8; j++) {
            int col = colBase + tx * 8 + j;
            float v = acc[i][j];
            if (EPI == 2) {
                v += bias[col];
                v = (v > 20.f) ? v : log1pf(__expf(v));
            }
            C[(size_t)row * ldc + col] = v;
        }
    }
}

// ---------------- small-N GEMM (x_proj: N=56, K=768) ----------------
__global__ __launch_bounds__(256) void sgemm_s(
    const float* __restrict__ A, int lda,
    const float* __restrict__ W, int K,
    float* __restrict__ C, int ldc, int N)
{
    __shared__ float As[16][32];
    __shared__ float Ws[16][64];
    int tid = threadIdx.x;
    int rowBase = blockIdx.y * 32;
    int colBase = blockIdx.x * 64;
    int ty = tid >> 4, tx = tid & 15;
    float acc[2][4] = {{0.f,0.f,0.f,0.f},{0.f,0.f,0.f,0.f}};
    int wn = tid >> 2, wk = (tid & 3) * 4;
    bool wv = (colBase + wn) < N;

    for (int k0 = 0; k0 < K; k0 += 16) {
        __syncthreads();
        #pragma unroll
        for (int i = tid; i < 512; i += 256) {
            int r = i >> 4, k = i & 15;
            As[k][r] = A[(size_t)(rowBase + r) * lda + k0 + k];
        }
        float4 wvv = wv ? *(const float4*)&W[(size_t)(colBase + wn) * K + k0 + wk]
                        : make_float4(0.f,0.f,0.f,0.f);
        Ws[wk+0][wn] = wvv.x; Ws[wk+1][wn] = wvv.y;
        Ws[wk+2][wn] = wvv.z; Ws[wk+3][wn] = wvv.w;
        __syncthreads();
        #pragma unroll
        for (int k = 0; k < 16; k++) {
            float a0 = As[k][ty], a1 = As[k][ty + 16];
            float4 w4 = *(const float4*)&Ws[k][tx*4];
            acc[0][0] = fmaf(a0, w4.x, acc[0][0]);
            acc[0][1] = fmaf(a0, w4.y, acc[0][1]);
            acc[0][2] = fmaf(a0, w4.z, acc[0][2]);
            acc[0][3] = fmaf(a0, w4.w, acc[0][3]);
            acc[1][0] = fmaf(a1, w4.x, acc[1][0]);
            acc[1][1] = fmaf(a1, w4.y, acc[1][1]);
            acc[1][2] = fmaf(a1, w4.z, acc[1][2]);
            acc[1][3] = fmaf(a1, w4.w, acc[1][3]);
        }
    }
    #pragma unroll
    for (int i = 0; i < 2; i++) {
        int row = rowBase + ty + i * 16;
        #pragma unroll
        for (int j = 0; j < 4; j++) {
            int col = colBase + tx * 4 + j;
            if (col < N) C[(size_t)row * ldc + col] = acc[i][j];
        }
    }
}

// ---------------- causal depthwise conv (k=4) + SiLU ----------------
__global__ void conv_kernel(const float* __restrict__ XZ,
                            const float* __restrict__ Wc,
                            const float* __restrict__ Bc,
                            float* __restrict__ XC, int dir)
{
    int idx = blockIdx.x * blockDim.x + threadIdx.x;
    if (idx >= ROWS * DI) return;
    int d = idx % DI;
    int t = (idx / DI) % LSEQ;
    int b = idx / (DI * LSEQ);
    const float* xm = XZ + (size_t)b * LSEQ * (2 * DI) + d;
    float acc = Bc[d];
    #pragma unroll
    for (int j = 0; j < 4; j++) {
        int tt = (dir == 0) ? (t - 3 + j) : (t + 3 - j);
        if (tt >= 0 && tt < LSEQ)
            acc = fmaf(Wc[d * 4 + j], xm[(size_t)tt * (2 * DI)], acc);
    }
    acc = acc / (1.f + __expf(-acc));
    XC[idx] = acc;
}

// ---------------- selective scan: 64-thr blocks, software prefetch ----------------
// grid (NB, 12); out rows of len 3*DI = [hi | hi | lo]
__global__ __launch_bounds__(64) void scan_kernel(
    const float* __restrict__ XC,
    const float* __restrict__ DT,
    const float* __restrict__ XDBL,
    const float* __restrict__ XZ,
    const float* __restrict__ Alog,
    const float* __restrict__ Dp,
    __nv_bfloat16* __restrict__ A3, int dir)
{
    __shared__ float Bs[LSEQ][DS];
    __shared__ float Cs[LSEQ][DS];
    int b = blockIdx.x;
    int d = blockIdx.y * 64 + threadIdx.x;

    const float* xd = XDBL + (size_t)b * LSEQ * XPD;
    for (int i = threadIdx.x; i < LSEQ * DS; i += 64) {
        int t = i / DS, n = i % DS;
        Bs[t][n] = xd[t * XPD + DTRK + n];
        Cs[t][n] = xd[t * XPD + DTRK + DS + n];
    }
    __syncthreads();

    float A[DS];
    #pragma unroll
    for (int n = 0; n < DS; n++) A[n] = -__expf(Alog[d * DS + n]);
    float Dd = Dp[d];
    float h[DS];
    #pragma unroll
    for (int n = 0; n < DS; n++) h[n] = 0.f;

    const float* ub  = XC + (size_t)b * LSEQ * DI + d;
    const float* dtb = DT + (size_t)b * LSEQ * DI + d;
    const float* zb  = XZ + (size_t)b * LSEQ * (2 * DI) + DI + d;

    int t = dir ? (LSEQ - 1) : 0;
    int step = dir ? -1 : 1;
    float dtv = dtb[(size_t)t * DI];
    float u   = ub[(size_t)t * DI];
    float z   = zb[(size_t)t * (2 * DI)];

    for (int s = 0; s < LSEQ; s++) {
        int tn = t + step;
        float dtn = 0.f, un = 0.f, zn = 0.f;
        if (s + 1 < LSEQ) {
            dtn = dtb[(size_t)tn * DI];
            un  = ub[(size_t)tn * DI];
            zn  = zb[(size_t)tn * (2 * DI)];
        }

        float du = dtv * u;
        float accv = 0.f;
        #pragma unroll
        for (int n = 0; n < DS; n++) {
            float dA = __expf(dtv * A[n]);
            h[n] = fmaf(dA, h[n], du * Bs[t][n]);
            accv = fmaf(h[n], Cs[t][n], accv);
        }
        float sz = z / (1.f + __expf(-z));
        float y = (accv + u * Dd) * sz;
        __nv_bfloat16 hi = __float2bfloat16(y);
        __nv_bfloat16 lo = __float2bfloat16(y - __bfloat162float(hi));
        size_t rb = ((size_t)b * LSEQ + t) * (3 * DI);
        A3[rb + d]          = hi;
        A3[rb + DI + d]     = hi;
        A3[rb + 2 * DI + d] = lo;

        dtv = dtn; u = un; z = zn; t = tn;
    }
}

// ---------------- final scatter ----------------
__global__ void final_kernel(const float* __restrict__ X,
                             const float* __restrict__ FUSED,
                             const int* __restrict__ inv_idx,
                             float* __restrict__ OUT)
{
    int idx = blockIdx.x * blockDim.x + threadIdx.x;
    if (idx >= NB * SEQF * DM) return;
    int c = idx % DM;
    int s = (idx / DM) % SEQF;
    int b = idx / (DM * SEQF);
    if (s == 0) {
        OUT[idx] = X[idx];
    } else {
        int src = inv_idx[s - 1];
        OUT[idx] = FUSED[((size_t)b * LSEQ + src) * DM + c];
    }
}

// ---------------- host launch ----------------
extern "C" void kernel_launch(void* const* d_in, const int* in_sizes, int n_in,
                              void* d_out, int out_size)
{
    float* S = nullptr;
    cudaGetSymbolAddress((void**)&S, g_scratch);

    float* pr    = S + OFF_PR;
    float* xz    = S + OFF_XZ;
    float* xc    = S + OFF_XC;
    float* xdbl  = S + OFF_XDBL;
    float* dtb   = S + OFF_DT;
    float* fused = S + OFF_FUSED;
    __nv_bfloat16* a3   = (__nv_bfloat16*)(S + OFF_ACT3);
    __nv_bfloat16* cat3 = (__nv_bfloat16*)(S + OFF_CAT3);
    __nv_bfloat16* w3   = (__nv_bfloat16*)(S + OFF_W3);

    const int SMEM_BG = STAGES * 128 * SKS * 2 * 2;   // 61440
    cudaFuncSetAttribute(bgemm<0>, cudaFuncAttributeMaxDynamicSharedMemorySize, SMEM_BG);
    cudaFuncSetAttribute(bgemm<1>, cudaFuncAttributeMaxDynamicSharedMemorySize, SMEM_BG);
    cudaFuncSetAttribute(bgemm<3>, cudaFuncAttributeMaxDynamicSharedMemorySize, SMEM_BG);

    const float* x        = (const float*)d_in[0];
    const float* fusion_w = (const float*)d_in[23];
    const float* fusion_b = (const float*)d_in[24];
    const int*   scan_idx = (const int*)d_in[25];
    const int*   inv_idx  = (const int*)d_in[26];

    gather_kernel<<<(ROWS*DM + 255)/256, 256>>>(x, scan_idx, pr);

    for (int dir = 0; dir < 2; dir++) {
        int base = 1 + dir * 11;
        const float* ln_g   = (const float*)d_in[base + 0];
        const float* ln_b   = (const float*)d_in[base + 1];
        const float* in_w   = (const float*)d_in[base + 2];   // (1536,384)
        const float* conv_w = (const float*)d_in[base + 3];
        const float* conv_b = (const float*)d_in[base + 4];
        const float* x_w    = (const float*)d_in[base + 5];   // (56,768)
        const float* dt_w   = (const float*)d_in[base + 6];   // (768,24)
        const float* dt_b   = (const float*)d_in[base + 7];
        const float* A_log  = (const float*)d_in[base + 8];
        const float* Dp     = (const float*)d_in[base + 9];
        const float* out_w  = (const float*)d_in[base + 10];  // (384,768)

        ln_split_kernel<<<ROWS, 128>>>(pr, ln_g, ln_b, a3);

        // in_proj: xz = xln @ in_w^T  (K'=1152, N=1536)
        split3_wt<<<(2*DI*DM + 255)/256, 256>>>(in_w, w3, 2*DI*DM, DM);
        bgemm<0><<<dim3(12, 48), 256, SMEM_BG>>>(a3, 3*DM, w3, 3*DM,
                                                 nullptr, nullptr, 0, xz, 2*DI,
                                                 nullptr, 0);

        conv_kernel<<<(ROWS*DI + 255)/256, 256>>>(xz, conv_w, conv_b, xc, dir);

        sgemm_s<<<dim3(1, ROWS/32), 256>>>(xc, DI, x_w, DI, xdbl, XPD, XPD);

        sgemm128<2><<<dim3(6, 48), 256>>>(xdbl, XPD, dt_w, DTRK, dt_b, dtb, DI);

        scan_kernel<<<dim3(NB, 12), 64>>>(xc, dtb, xdbl, xz, A_log, Dp, a3, dir);

        // out_proj: cat3[:, dir cols] = split(y @ out_w^T + pr)  (K'=2304, N=384)
        split3_wt<<<(DM*DI + 255)/256, 256>>>(out_w, w3, DM*DI, DI);
        bgemm<3><<<dim3(3, 48), 256, SMEM_BG>>>(a3, 3*DI, w3, 3*DI,
                                                nullptr, pr, DM, nullptr, 0,
                                                cat3, dir * DM);
    }

    // fusion: fused = cat @ fusion_w^T + fusion_b  (K'=2304, N=384)
    split3_wt<<<(DM*DI + 255)/256, 256>>>(fusion_w, w3, DM*DI, DI);
    bgemm<1><<<dim3(3, 48), 256, SMEM_BG>>>(cat3, 2304, w3, 3*(2*DM),
                                            fusion_b, nullptr, 0, fused, DM,
                                            nullptr, 0);

    final_kernel<<<(NB*SEQF*DM + 255)/256, 256>>>(x, fused, inv_idx, (float*)d_out);
}

// round 12
// speedup vs baseline: 1.3160x; 1.2285x over previous
#include <cuda_runtime.h>
#include <cuda_bf16.h>
#include <math.h>

// ---------------- problem constants ----------------
#define NB    32
#define LSEQ  192
#define SEQF  193
#define DM    384
#define DI    768
#define DS    16
#define DTRK  24
#define XPD   56
#define ROWS  (NB*LSEQ)   // 6144

// ---------------- scratch (floats), per-dir buffers for z-batching ----------------
__device__ float g_scratch[67485696];

#define OFF_PR     0            //  2359296
#define OFF_XZ     2359296      // 2x9437184
#define OFF_XC     21233664     // 2x4718592
#define OFF_XDBL   30670848     // 2x344064
#define OFF_DT     31358976     // 2x4718592
#define OFF_FUSED  40796160     //  2359296
#define OFF_ACT3   43155456     // 2x7077888
#define OFF_CAT3   57311232     //  7077888
#define OFF_W3IN   64389120     // 2x884736
#define OFF_W3OUT  66158592     // 2x442368
#define OFF_W3FUS  67043328     //  442368

// z-strides (elements)
#define ZS_XZ   ((size_t)ROWS*1536)        // floats
#define ZS_XC   ((size_t)ROWS*768)
#define ZS_XD   ((size_t)ROWS*XPD)
#define ZS_DT   ((size_t)ROWS*768)
#define ZS_A3   ((size_t)ROWS*2304)        // bf16
#define ZS_W3IN ((size_t)1536*1152)        // bf16
#define ZS_W3OUT ((size_t)384*2304)        // bf16

// ---------------- gather ----------------
__global__ void gather_kernel(const float* __restrict__ X,
                              const int* __restrict__ scan_idx,
                              float* __restrict__ PR)
{
    int idx = blockIdx.x * blockDim.x + threadIdx.x;
    if (idx >= ROWS * DM) return;
    int c = idx % DM;
    int t = (idx / DM) % LSEQ;
    int b = idx / (DM * LSEQ);
    int src = scan_idx[t];
    PR[idx] = X[((size_t)b * SEQF + 1 + src) * DM + c];
}

// ---------------- layernorm + 3-block split, both dirs (blockIdx.y = dir) --------
__global__ __launch_bounds__(128) void ln_split_kernel(
    const float* __restrict__ X,
    const float* __restrict__ G0, const float* __restrict__ B0,
    const float* __restrict__ G1, const float* __restrict__ B1,
    __nv_bfloat16* __restrict__ A3)
{
    int row = blockIdx.x;
    int dir = blockIdx.y;
    const float* G  = dir ? G1 : G0;
    const float* Bb = dir ? B1 : B0;
    const float* x = X + (size_t)row * DM;
    float v[3]; float s = 0.f, ss = 0.f;
    #pragma unroll
    for (int i = 0; i < 3; i++) {
        v[i] = x[threadIdx.x + i * 128];
        s += v[i]; ss += v[i] * v[i];
    }
    __shared__ float sh_s[4], sh_ss[4];
    #pragma unroll
    for (int o = 16; o; o >>= 1) {
        s  += __shfl_down_sync(0xffffffffu, s,  o);
        ss += __shfl_down_sync(0xffffffffu, ss, o);
    }
    int wid = threadIdx.x >> 5, lid = threadIdx.x & 31;
    if (lid == 0) { sh_s[wid] = s; sh_ss[wid] = ss; }
    __syncthreads();
    float ts = sh_s[0] + sh_s[1] + sh_s[2] + sh_s[3];
    float tss = sh_ss[0] + sh_ss[1] + sh_ss[2] + sh_ss[3];
    float mean = ts * (1.f / DM);
    float var = tss * (1.f / DM) - mean * mean;
    float rstd = rsqrtf(var + 1e-5f);
    __nv_bfloat16* a = A3 + (size_t)dir * ZS_A3 + (size_t)row * (3 * DM);
    #pragma unroll
    for (int i = 0; i < 3; i++) {
        int c = threadIdx.x + i * 128;
        float y = (v[i] - mean) * rstd * G[c] + Bb[c];
        __nv_bfloat16 hi = __float2bfloat16(y);
        __nv_bfloat16 lo = __float2bfloat16(y - __bfloat162float(hi));
        a[c]          = hi;
        a[DM + c]     = hi;
        a[2 * DM + c] = lo;
    }
}

// ---------------- weight 3-block split, 2 sources (blockIdx.y selects) ----------
__global__ void split3_wt2(const float* __restrict__ X0,
                           const float* __restrict__ X1,
                           __nv_bfloat16* __restrict__ Y,
                           int total, int K, size_t strideY)
{
    int idx = blockIdx.x * blockDim.x + threadIdx.x;
    if (idx >= total) return;
    int dir = blockIdx.y;
    const float* X = dir ? X1 : X0;
    __nv_bfloat16* Yd = Y + (size_t)dir * strideY;
    int m = idx / K, k = idx % K;
    float x = X[idx];
    __nv_bfloat16 hi = __float2bfloat16(x);
    __nv_bfloat16 lo = __float2bfloat16(x - __bfloat162float(hi));
    size_t r = (size_t)m * (3 * K);
    Yd[r + k]         = hi;
    Yd[r + K + k]     = lo;
    Yd[r + 2 * K + k] = hi;
}

// ---------------- mma / cp.async helpers ----------------
__device__ __forceinline__ void mma16816(float* c, const unsigned* a, const unsigned* b)
{
    asm volatile(
        "mma.sync.aligned.m16n8k16.row.col.f32.bf16.bf16.f32 "
        "{%0,%1,%2,%3}, {%4,%5,%6,%7}, {%8,%9}, {%0,%1,%2,%3};\n"
        : "+f"(c[0]), "+f"(c[1]), "+f"(c[2]), "+f"(c[3])
        : "r"(a[0]), "r"(a[1]), "r"(a[2]), "r"(a[3]), "r"(b[0]), "r"(b[1]));
}
__device__ __forceinline__ void ldsmx4(unsigned* r, unsigned addr)
{
    asm volatile("ldmatrix.sync.aligned.m8n8.x4.shared.b16 {%0,%1,%2,%3}, [%4];"
                 : "=r"(r[0]), "=r"(r[1]), "=r"(r[2]), "=r"(r[3]) : "r"(addr));
}
__device__ __forceinline__ void ldsmx2(unsigned* r, unsigned addr)
{
    asm volatile("ldmatrix.sync.aligned.m8n8.x2.shared.b16 {%0,%1}, [%2];"
                 : "=r"(r[0]), "=r"(r[1]) : "r"(addr));
}
__device__ __forceinline__ void cpa16(unsigned dst, const void* src)
{
    asm volatile("cp.async.cg.shared.global [%0], [%1], 16;\n" :: "r"(dst), "l"(src));
}
__device__ __forceinline__ void cpa_commit()
{
    asm volatile("cp.async.commit_group;\n");
}
template<int N>
__device__ __forceinline__ void cpa_wait()
{
    asm volatile("cp.async.wait_group %0;\n" :: "n"(N));
}

// split-bf16 store for out_proj epilogue (cat3 row = 2304 bf16: [hi|hi|lo])
__device__ __forceinline__ void split_store2(__nv_bfloat16* C3, int row, int colL,
                                             float s0, float s1)
{
    __nv_bfloat16 h0 = __float2bfloat16(s0);
    __nv_bfloat16 h1 = __float2bfloat16(s1);
    __nv_bfloat16 l0 = __float2bfloat16(s0 - __bfloat162float(h0));
    __nv_bfloat16 l1 = __float2bfloat16(s1 - __bfloat162float(h1));
    __nv_bfloat162 hp; hp.x = h0; hp.y = h1;
    __nv_bfloat162 lp; lp.x = l0; lp.y = l1;
    size_t rb = (size_t)row * 2304;
    *(__nv_bfloat162*)&C3[rb + colL]        = hp;
    *(__nv_bfloat162*)&C3[rb + 768 + colL]  = hp;
    *(__nv_bfloat162*)&C3[rb + 1536 + colL] = lp;
}

// ---------------- 3-stage pipelined bf16 tensor GEMM, BN=128, z-batched ----------
// EPI: 0 none (fp32 C), 1 +bias (fp32 C), 3 +residual then split-bf16 store to C3
#define SKS 40
#define TILEB (128 * SKS * 2)
#define STAGES 3
template<int EPI>
__global__ __launch_bounds__(256, 2) void bgemm(
    const __nv_bfloat16* __restrict__ A2, int lda, size_t zsA,
    const __nv_bfloat16* __restrict__ W2, int K2, size_t zsW,
    const float* __restrict__ bias,
    const float* __restrict__ R, int ldr,
    float* __restrict__ C, int ldc, size_t zsC,
    __nv_bfloat16* __restrict__ C3, int zDirOff)
{
    extern __shared__ __nv_bfloat16 dsm[];
    __nv_bfloat16* Asm = dsm;
    __nv_bfloat16* Wsm = dsm + STAGES * 128 * SKS;

    int zz = blockIdx.z;
    A2 += (size_t)zz * zsA;
    W2 += (size_t)zz * zsW;
    C  += (size_t)zz * zsC;
    int dirOff = zz * zDirOff;

    int tid = threadIdx.x;
    int lane = tid & 31;
    int warp = tid >> 5;
    int rowBase = blockIdx.y * 128;
    int colBase = blockIdx.x * 128;
    int warpM = (warp >> 2) * 64;
    int warpN = (warp & 3) * 32;

    int r0 = tid >> 2, c0 = (tid & 3) * 8;
    const __nv_bfloat16* Ap0 = A2 + (size_t)(rowBase + r0) * lda + c0;
    const __nv_bfloat16* Ap1 = A2 + (size_t)(rowBase + r0 + 64) * lda + c0;
    const __nv_bfloat16* Wp0 = W2 + (size_t)(colBase + r0) * K2 + c0;
    const __nv_bfloat16* Wp1 = W2 + (size_t)(colBase + r0 + 64) * K2 + c0;

    unsigned sA = (unsigned)__cvta_generic_to_shared(Asm);
    unsigned sW = (unsigned)__cvta_generic_to_shared(Wsm);
    unsigned stA0 = sA + (r0 * SKS + c0) * 2;
    unsigned stA1 = sA + ((r0 + 64) * SKS + c0) * 2;
    unsigned stW0 = sW + (r0 * SKS + c0) * 2;
    unsigned stW1 = sW + ((r0 + 64) * SKS + c0) * 2;

    float acc[4][4][4];
    #pragma unroll
    for (int i = 0; i < 4; i++)
        #pragma unroll
        for (int j = 0; j < 4; j++)
            #pragma unroll
            for (int q = 0; q < 4; q++) acc[i][j][q] = 0.f;

    int l16 = lane & 15;
    unsigned aAddrBase = sA + ((warpM + l16) * SKS + (lane >> 4) * 8) * 2;
    unsigned wAddrBase = sW + ((warpN + (l16 & 7)) * SKS + ((l16 >> 3) & 1) * 8) * 2;

    int nIter = K2 >> 5;

    cpa16(stA0, Ap0); cpa16(stA1, Ap1);
    cpa16(stW0, Wp0); cpa16(stW1, Wp1);
    cpa_commit();
    {
        unsigned off = TILEB;
        cpa16(stA0 + off, Ap0 + 32); cpa16(stA1 + off, Ap1 + 32);
        cpa16(stW0 + off, Wp0 + 32); cpa16(stW1 + off, Wp1 + 32);
        cpa_commit();
    }

    int bufc = 0, bufn = 2;
    for (int it = 0; it < nIter; it++) {
        if (it + 1 < nIter) cpa_wait<1>(); else cpa_wait<0>();
        __syncthreads();
        if (it + 2 < nIter) {
            int ko = (it + 2) << 5;
            unsigned off = bufn * TILEB;
            cpa16(stA0 + off, Ap0 + ko); cpa16(stA1 + off, Ap1 + ko);
            cpa16(stW0 + off, Wp0 + ko); cpa16(stW1 + off, Wp1 + ko);
            cpa_commit();
        }

        unsigned aB = aAddrBase + bufc * TILEB;
        unsigned wB = wAddrBase + bufc * TILEB;
        #pragma unroll
        for (int kk = 0; kk < 32; kk += 16) {
            unsigned b[4][2];
            #pragma unroll
            for (int j = 0; j < 4; j++)
                ldsmx2(b[j], wB + (j * 8 * SKS + kk) * 2);
            #pragma unroll
            for (int i = 0; i < 4; i++) {
                unsigned a[4];
                ldsmx4(a, aB + (i * 16 * SKS + kk) * 2);
                #pragma unroll
                for (int j = 0; j < 4; j++)
                    mma16816(acc[i][j], a, b[j]);
            }
        }
        bufc = (bufc + 1 == STAGES) ? 0 : bufc + 1;
        bufn = (bufn + 1 == STAGES) ? 0 : bufn + 1;
    }

    int erow = lane >> 2;
    int ecol = (lane & 3) * 2;
    #pragma unroll
    for (int i = 0; i < 4; i++) {
        int row = rowBase + warpM + i * 16 + erow;
        #pragma unroll
        for (int j = 0; j < 4; j++) {
            int col = colBase + warpN + j * 8 + ecol;
            float v0 = acc[i][j][0], v1 = acc[i][j][1];
            float v2 = acc[i][j][2], v3 = acc[i][j][3];
            if (EPI == 1) {
                float b0 = bias[col], b1 = bias[col + 1];
                v0 += b0; v1 += b1; v2 += b0; v3 += b1;
            }
            if (EPI == 3) {
                v0 += R[(size_t)row * ldr + col];
                v1 += R[(size_t)row * ldr + col + 1];
                v2 += R[(size_t)(row + 8) * ldr + col];
                v3 += R[(size_t)(row + 8) * ldr + col + 1];
                split_store2(C3, row,     dirOff + col, v0, v1);
                split_store2(C3, row + 8, dirOff + col, v2, v3);
            } else {
                C[(size_t)row * ldc + col]           = v0;
                C[(size_t)row * ldc + col + 1]       = v1;
                C[(size_t)(row + 8) * ldc + col]     = v2;
                C[(size_t)(row + 8) * ldc + col + 1] = v3;
            }
        }
    }
}

// ---------------- fp32 SGEMM (dt GEMM, K=24), z-batched ----------------
__global__ __launch_bounds__(256) void sgemm128_dt(
    const float* __restrict__ A, int lda, size_t zsA,
    const float* __restrict__ W0, const float* __restrict__ W1, int K,
    const float* __restrict__ bias0, const float* __restrict__ bias1,
    float* __restrict__ C, int ldc, size_t zsC)
{
    __shared__ float As[8][128];
    __shared__ float Ws[8][128];
    int zz = blockIdx.z;
    const float* W = zz ? W1 : W0;
    const float* bias = zz ? bias1 : bias0;
    A += (size_t)zz * zsA;
    C += (size_t)zz * zsC;

    int tid = threadIdx.x;
    int rowBase = blockIdx.y * 128;
    int colBase = blockIdx.x * 128;
    int ty = tid >> 4, tx = tid & 15;
    int arow = tid >> 1;
    int ak   = (tid & 1) * 4;

    float acc[8][8];
    #pragma unroll
    for (int i = 0; i < 8; i++)
        #pragma unroll
        for (int j = 0; j < 8; j++) acc[i][j] = 0.f;

    const float* Aptr = A + (size_t)(rowBase + arow) * lda + ak;
    const float* Wptr = W + (size_t)(colBase + arow) * K + ak;

    for (int k0 = 0; k0 < K; k0 += 8) {
        float4 av = *(const float4*)(Aptr + k0);
        float4 wv = *(const float4*)(Wptr + k0);
        __syncthreads();
        As[ak+0][arow] = av.x; As[ak+1][arow] = av.y;
        As[ak+2][arow] = av.z; As[ak+3][arow] = av.w;
        Ws[ak+0][arow] = wv.x; Ws[ak+1][arow] = wv.y;
        Ws[ak+2][arow] = wv.z; Ws[ak+3][arow] = wv.w;
        __syncthreads();
        #pragma unroll
        for (int k = 0; k < 8; k++) {
            float a[8], w[8];
            *(float4*)&a[0] = *(const float4*)&As[k][ty*8];
            *(float4*)&a[4] = *(const float4*)&As[k][ty*8+4];
            *(float4*)&w[0] = *(const float4*)&Ws[k][tx*8];
            *(float4*)&w[4] = *(const float4*)&Ws[k][tx*8+4];
            #pragma unroll
            for (int i = 0; i < 8; i++)
                #pragma unroll
                for (int j = 0; j < 8; j++)
                    acc[i][j] = fmaf(a[i], w[j], acc[i][j]);
        }
    }
    #pragma unroll
    for (int i = 0; i < 8; i++) {
        int row = rowBase + ty * 8 + i;
        #pragma unroll
        for (int j = 0; j < 8; j++) {
            int col = colBase + tx * 8 + j;
            float v = acc[i][j] + bias[col];
            v = (v > 20.f) ? v : log1pf(__expf(v));
            C[(size_t)row * ldc + col] = v;
        }
    }
}

// ---------------- small-N GEMM (x_proj: N=56, K=768), z-batched ----------------
__global__ __launch_bounds__(256) void sgemm_s(
    const float* __restrict__ A, int lda, size_t zsA,
    const float* __restrict__ W0, const float* __restrict__ W1, int K,
    float* __restrict__ C, int ldc, size_t zsC, int N)
{
    __shared__ float As[16][32];
    __shared__ float Ws[16][64];
    int zz = blockIdx.z;
    const float* W = zz ? W1 : W0;
    A += (size_t)zz * zsA;
    C += (size_t)zz * zsC;

    int tid = threadIdx.x;
    int rowBase = blockIdx.y * 32;
    int colBase = blockIdx.x * 64;
    int ty = tid >> 4, tx = tid & 15;
    float acc[2][4] = {{0.f,0.f,0.f,0.f},{0.f,0.f,0.f,0.f}};
    int wn = tid >> 2, wk = (tid & 3) * 4;
    bool wv = (colBase + wn) < N;

    for (int k0 = 0; k0 < K; k0 += 16) {
        __syncthreads();
        #pragma unroll
        for (int i = tid; i < 512; i += 256) {
            int r = i >> 4, k = i & 15;
            As[k][r] = A[(size_t)(rowBase + r) * lda + k0 + k];
        }
        float4 wvv = wv ? *(const float4*)&W[(size_t)(colBase + wn) * K + k0 + wk]
                        : make_float4(0.f,0.f,0.f,0.f);
        Ws[wk+0][wn] = wvv.x; Ws[wk+1][wn] = wvv.y;
        Ws[wk+2][wn] = wvv.z; Ws[wk+3][wn] = wvv.w;
        __syncthreads();
        #pragma unroll
        for (int k = 0; k < 16; k++) {
            float a0 = As[k][ty], a1 = As[k][ty + 16];
            float4 w4 = *(const float4*)&Ws[k][tx*4];
            acc[0][0] = fmaf(a0, w4.x, acc[0][0]);
            acc[0][1] = fmaf(a0, w4.y, acc[0][1]);
            acc[0][2] = fmaf(a0, w4.z, acc[0][2]);
            acc[0][3] = fmaf(a0, w4.w, acc[0][3]);
            acc[1][0] = fmaf(a1, w4.x, acc[1][0]);
            acc[1][1] = fmaf(a1, w4.y, acc[1][1]);
            acc[1][2] = fmaf(a1, w4.z, acc[1][2]);
            acc[1][3] = fmaf(a1, w4.w, acc[1][3]);
        }
    }
    #pragma unroll
    for (int i = 0; i < 2; i++) {
        int row = rowBase + ty + i * 16;
        #pragma unroll
        for (int j = 0; j < 4; j++) {
            int col = colBase + tx * 4 + j;
            if (col < N) C[(size_t)row * ldc + col] = acc[i][j];
        }
    }
}

// ---------------- causal depthwise conv (k=4) + SiLU, z-batched ----------------
__global__ void conv_kernel(const float* __restrict__ XZ,
                            const float* __restrict__ Wc0, const float* __restrict__ Bc0,
                            const float* __restrict__ Wc1, const float* __restrict__ Bc1,
                            float* __restrict__ XC)
{
    int idx = blockIdx.x * blockDim.x + threadIdx.x;
    if (idx >= ROWS * DI) return;
    int dir = blockIdx.y;
    const float* Wc = dir ? Wc1 : Wc0;
    const float* Bc = dir ? Bc1 : Bc0;
    const float* XZd = XZ + (size_t)dir * ZS_XZ;
    float* XCd = XC + (size_t)dir * ZS_XC;

    int d = idx % DI;
    int t = (idx / DI) % LSEQ;
    int b = idx / (DI * LSEQ);
    const float* xm = XZd + (size_t)b * LSEQ * (2 * DI) + d;
    float acc = Bc[d];
    #pragma unroll
    for (int j = 0; j < 4; j++) {
        int tt = (dir == 0) ? (t - 3 + j) : (t + 3 - j);
        if (tt >= 0 && tt < LSEQ)
            acc = fmaf(Wc[d * 4 + j], xm[(size_t)tt * (2 * DI)], acc);
    }
    acc = acc / (1.f + __expf(-acc));
    XCd[idx] = acc;
}

// ---------------- selective scan, z-batched: grid (NB, 12, 2) ----------------
__global__ __launch_bounds__(64) void scan_kernel(
    const float* __restrict__ XC,
    const float* __restrict__ DT,
    const float* __restrict__ XDBL,
    const float* __restrict__ XZ,
    const float* __restrict__ Alog0, const float* __restrict__ Dp0,
    const float* __restrict__ Alog1, const float* __restrict__ Dp1,
    __nv_bfloat16* __restrict__ A3)
{
    __shared__ float Bs[LSEQ][DS];
    __shared__ float Cs[LSEQ][DS];
    int b = blockIdx.x;
    int dir = blockIdx.z;
    int d = blockIdx.y * 64 + threadIdx.x;

    const float* Alog = dir ? Alog1 : Alog0;
    const float* Dp   = dir ? Dp1 : Dp0;
    const float* XCd   = XC + (size_t)dir * ZS_XC;
    const float* DTd   = DT + (size_t)dir * ZS_DT;
    const float* XDBLd = XDBL + (size_t)dir * ZS_XD;
    const float* XZd   = XZ + (size_t)dir * ZS_XZ;
    __nv_bfloat16* A3d = A3 + (size_t)dir * ZS_A3;

    const float* xd = XDBLd + (size_t)b * LSEQ * XPD;
    for (int i = threadIdx.x; i < LSEQ * DS; i += 64) {
        int t = i / DS, n = i % DS;
        Bs[t][n] = xd[t * XPD + DTRK + n];
        Cs[t][n] = xd[t * XPD + DTRK + DS + n];
    }
    __syncthreads();

    float A[DS];
    #pragma unroll
    for (int n = 0; n < DS; n++) A[n] = -__expf(Alog[d * DS + n]);
    float Dd = Dp[d];
    float h[DS];
    #pragma unroll
    for (int n = 0; n < DS; n++) h[n] = 0.f;

    const float* ub  = XCd + (size_t)b * LSEQ * DI + d;
    const float* dtb = DTd + (size_t)b * LSEQ * DI + d;
    const float* zb  = XZd + (size_t)b * LSEQ * (2 * DI) + DI + d;

    int t = dir ? (LSEQ - 1) : 0;
    int step = dir ? -1 : 1;
    float dtv = dtb[(size_t)t * DI];
    float u   = ub[(size_t)t * DI];
    float z   = zb[(size_t)t * (2 * DI)];

    for (int s = 0; s < LSEQ; s++) {
        int tn = t + step;
        float dtn = 0.f, un = 0.f, zn = 0.f;
        if (s + 1 < LSEQ) {
            dtn = dtb[(size_t)tn * DI];
            un  = ub[(size_t)tn * DI];
            zn  = zb[(size_t)tn * (2 * DI)];
        }

        float du = dtv * u;
        float accv = 0.f;
        #pragma unroll
        for (int n = 0; n < DS; n++) {
            float dA = __expf(dtv * A[n]);
            h[n] = fmaf(dA, h[n], du * Bs[t][n]);
            accv = fmaf(h[n], Cs[t][n], accv);
        }
        float sz = z / (1.f + __expf(-z));
        float y = (accv + u * Dd) * sz;
        __nv_bfloat16 hi = __float2bfloat16(y);
        __nv_bfloat16 lo = __float2bfloat16(y - __bfloat162float(hi));
        size_t rb = ((size_t)b * LSEQ + t) * (3 * DI);
        A3d[rb + d]          = hi;
        A3d[rb + DI + d]     = hi;
        A3d[rb + 2 * DI + d] = lo;

        dtv = dtn; u = un; z = zn; t = tn;
    }
}

// ---------------- final scatter ----------------
__global__ void final_kernel(const float* __restrict__ X,
                             const float* __restrict__ FUSED,
                             const int* __restrict__ inv_idx,
                             float* __restrict__ OUT)
{
    int idx = blockIdx.x * blockDim.x + threadIdx.x;
    if (idx >= NB * SEQF * DM) return;
    int c = idx % DM;
    int s = (idx / DM) % SEQF;
    int b = idx / (DM * SEQF);
    if (s == 0) {
        OUT[idx] = X[idx];
    } else {
        int src = inv_idx[s - 1];
        OUT[idx] = FUSED[((size_t)b * LSEQ + src) * DM + c];
    }
}

// ---------------- host launch ----------------
extern "C" void kernel_launch(void* const* d_in, const int* in_sizes, int n_in,
                              void* d_out, int out_size)
{
    float* S = nullptr;
    cudaGetSymbolAddress((void**)&S, g_scratch);

    float* pr    = S + OFF_PR;
    float* xz    = S + OFF_XZ;
    float* xc    = S + OFF_XC;
    float* xdbl  = S + OFF_XDBL;
    float* dtb   = S + OFF_DT;
    float* fused = S + OFF_FUSED;
    __nv_bfloat16* a3    = (__nv_bfloat16*)(S + OFF_ACT3);
    __nv_bfloat16* cat3  = (__nv_bfloat16*)(S + OFF_CAT3);
    __nv_bfloat16* w3in  = (__nv_bfloat16*)(S + OFF_W3IN);
    __nv_bfloat16* w3out = (__nv_bfloat16*)(S + OFF_W3OUT);
    __nv_bfloat16* w3fus = (__nv_bfloat16*)(S + OFF_W3FUS);

    const int SMEM_BG = STAGES * 128 * SKS * 2 * 2;   // 61440
    cudaFuncSetAttribute(bgemm<0>, cudaFuncAttributeMaxDynamicSharedMemorySize, SMEM_BG);
    cudaFuncSetAttribute(bgemm<1>, cudaFuncAttributeMaxDynamicSharedMemorySize, SMEM_BG);
    cudaFuncSetAttribute(bgemm<3>, cudaFuncAttributeMaxDynamicSharedMemorySize, SMEM_BG);

    const float* x        = (const float*)d_in[0];
    const float* f_ln_g   = (const float*)d_in[1];
    const float* f_ln_b   = (const float*)d_in[2];
    const float* f_in_w   = (const float*)d_in[3];
    const float* f_conv_w = (const float*)d_in[4];
    const float* f_conv_b = (const float*)d_in[5];
    const float* f_x_w    = (const float*)d_in[6];
    const float* f_dt_w   = (const float*)d_in[7];
    const float* f_dt_b   = (const float*)d_in[8];
    const float* f_A_log  = (const float*)d_in[9];
    const float* f_Dp     = (const float*)d_in[10];
    const float* f_out_w  = (const float*)d_in[11];
    const float* b_ln_g   = (const float*)d_in[12];
    const float* b_ln_b   = (const float*)d_in[13];
    const float* b_in_w   = (const float*)d_in[14];
    const float* b_conv_w = (const float*)d_in[15];
    const float* b_conv_b = (const float*)d_in[16];
    const float* b_x_w    = (const float*)d_in[17];
    const float* b_dt_w   = (const float*)d_in[18];
    const float* b_dt_b   = (const float*)d_in[19];
    const float* b_A_log  = (const float*)d_in[20];
    const float* b_Dp     = (const float*)d_in[21];
    const float* b_out_w  = (const float*)d_in[22];
    const float* fusion_w = (const float*)d_in[23];
    const float* fusion_b = (const float*)d_in[24];
    const int*   scan_idx = (const int*)d_in[25];
    const int*   inv_idx  = (const int*)d_in[26];

    gather_kernel<<<(ROWS*DM + 255)/256, 256>>>(x, scan_idx, pr);

    // LN + act split, both dirs
    ln_split_kernel<<<dim3(ROWS, 2), 128>>>(pr, f_ln_g, f_ln_b, b_ln_g, b_ln_b, a3);

    // weight splits (both dirs each)
    split3_wt2<<<dim3((2*DI*DM + 255)/256, 2), 256>>>(f_in_w, b_in_w, w3in,
                                                      2*DI*DM, DM, ZS_W3IN);
    split3_wt2<<<dim3((DM*DI + 255)/256, 2), 256>>>(f_out_w, b_out_w, w3out,
                                                    DM*DI, DI, ZS_W3OUT);
    split3_wt2<<<dim3((DM*DI + 255)/256, 1), 256>>>(fusion_w, fusion_w, w3fus,
                                                    DM*DI, DI, 0);

    // in_proj both dirs: (K'=1152, N=1536)
    bgemm<0><<<dim3(12, 48, 2), 256, SMEM_BG>>>(a3, 3*DM, ZS_A3,
                                                w3in, 3*DM, ZS_W3IN,
                                                nullptr, nullptr, 0,
                                                xz, 2*DI, ZS_XZ,
                                                nullptr, 0);

    // conv both dirs
    conv_kernel<<<dim3((ROWS*DI + 255)/256, 2), 256>>>(xz, f_conv_w, f_conv_b,
                                                       b_conv_w, b_conv_b, xc);

    // x_proj both dirs
    sgemm_s<<<dim3(1, ROWS/32, 2), 256>>>(xc, DI, ZS_XC, f_x_w, b_x_w, DI,
                                          xdbl, XPD, ZS_XD, XPD);

    // dt both dirs
    sgemm128_dt<<<dim3(6, 48, 2), 256>>>(xdbl, XPD, ZS_XD, f_dt_w, b_dt_w, DTRK,
                                         f_dt_b, b_dt_b, dtb, DI, ZS_DT);

    // scan both dirs
    scan_kernel<<<dim3(NB, 12, 2), 64>>>(xc, dtb, xdbl, xz,
                                         f_A_log, f_Dp, b_A_log, b_Dp, a3);

    // out_proj both dirs: (K'=2304, N=384) -> cat3 (cols offset z*384)
    bgemm<3><<<dim3(3, 48, 2), 256, SMEM_BG>>>(a3, 3*DI, ZS_A3,
                                               w3out, 3*DI, ZS_W3OUT,
                                               nullptr, pr, DM,
                                               nullptr, 0, 0,
                                               cat3, DM);

    // fusion: (K'=2304, N=384)
    bgemm<1><<<dim3(3, 48, 1), 256, SMEM_BG>>>(cat3, 2304, 0,
                                               w3fus, 3*(2*DM), 0,
                                               fusion_b, nullptr, 0,
                                               fused, DM, 0,
                                               nullptr, 0);

    final_kernel<<<(NB*SEQF*DM + 255)/256, 256>>>(x, fused, inv_idx, (float*)d_out);
}

// round 13
// speedup vs baseline: 1.3623x; 1.0352x over previous
#include <cuda_runtime.h>
#include <cuda_bf16.h>
#include <math.h>

// ---------------- problem constants ----------------
#define NB    32
#define LSEQ  192
#define SEQF  193
#define DM    384
#define DI    768
#define DS    16
#define DTRK  24
#define XPD   56
#define ROWS  (NB*LSEQ)   // 6144

// ---------------- scratch (floats), per-dir buffers for z-batching ----------------
__device__ float g_scratch[67485696];

#define OFF_PR     0
#define OFF_XZ     2359296
#define OFF_XC     21233664
#define OFF_XDBL   30670848
#define OFF_DT     31358976
#define OFF_FUSED  40796160
#define OFF_ACT3   43155456
#define OFF_CAT3   57311232
#define OFF_W3IN   64389120
#define OFF_W3OUT  66158592
#define OFF_W3FUS  67043328

// z-strides (elements)
#define ZS_XZ   ((size_t)ROWS*1536)
#define ZS_XC   ((size_t)ROWS*768)
#define ZS_XD   ((size_t)ROWS*XPD)
#define ZS_DT   ((size_t)ROWS*768)
#define ZS_A3   ((size_t)ROWS*2304)
#define ZS_W3IN ((size_t)1536*1152)
#define ZS_W3OUT ((size_t)384*2304)

// ---------------- gather ----------------
__global__ void gather_kernel(const float* __restrict__ X,
                              const int* __restrict__ scan_idx,
                              float* __restrict__ PR)
{
    int idx = blockIdx.x * blockDim.x + threadIdx.x;
    if (idx >= ROWS * DM) return;
    int c = idx % DM;
    int t = (idx / DM) % LSEQ;
    int b = idx / (DM * LSEQ);
    int src = scan_idx[t];
    PR[idx] = X[((size_t)b * SEQF + 1 + src) * DM + c];
}

// ---------------- layernorm + 3-block split, both dirs (blockIdx.y = dir) --------
__global__ __launch_bounds__(128) void ln_split_kernel(
    const float* __restrict__ X,
    const float* __restrict__ G0, const float* __restrict__ B0,
    const float* __restrict__ G1, const float* __restrict__ B1,
    __nv_bfloat16* __restrict__ A3)
{
    int row = blockIdx.x;
    int dir = blockIdx.y;
    const float* G  = dir ? G1 : G0;
    const float* Bb = dir ? B1 : B0;
    const float* x = X + (size_t)row * DM;
    float v[3]; float s = 0.f, ss = 0.f;
    #pragma unroll
    for (int i = 0; i < 3; i++) {
        v[i] = x[threadIdx.x + i * 128];
        s += v[i]; ss += v[i] * v[i];
    }
    __shared__ float sh_s[4], sh_ss[4];
    #pragma unroll
    for (int o = 16; o; o >>= 1) {
        s  += __shfl_down_sync(0xffffffffu, s,  o);
        ss += __shfl_down_sync(0xffffffffu, ss, o);
    }
    int wid = threadIdx.x >> 5, lid = threadIdx.x & 31;
    if (lid == 0) { sh_s[wid] = s; sh_ss[wid] = ss; }
    __syncthreads();
    float ts = sh_s[0] + sh_s[1] + sh_s[2] + sh_s[3];
    float tss = sh_ss[0] + sh_ss[1] + sh_ss[2] + sh_ss[3];
    float mean = ts * (1.f / DM);
    float var = tss * (1.f / DM) - mean * mean;
    float rstd = rsqrtf(var + 1e-5f);
    __nv_bfloat16* a = A3 + (size_t)dir * ZS_A3 + (size_t)row * (3 * DM);
    #pragma unroll
    for (int i = 0; i < 3; i++) {
        int c = threadIdx.x + i * 128;
        float y = (v[i] - mean) * rstd * G[c] + Bb[c];
        __nv_bfloat16 hi = __float2bfloat16(y);
        __nv_bfloat16 lo = __float2bfloat16(y - __bfloat162float(hi));
        a[c]          = hi;
        a[DM + c]     = hi;
        a[2 * DM + c] = lo;
    }
}

// ---------------- weight 3-block split, 2 sources ----------
__global__ void split3_wt2(const float* __restrict__ X0,
                           const float* __restrict__ X1,
                           __nv_bfloat16* __restrict__ Y,
                           int total, int K, size_t strideY)
{
    int idx = blockIdx.x * blockDim.x + threadIdx.x;
    if (idx >= total) return;
    int dir = blockIdx.y;
    const float* X = dir ? X1 : X0;
    __nv_bfloat16* Yd = Y + (size_t)dir * strideY;
    int m = idx / K, k = idx % K;
    float x = X[idx];
    __nv_bfloat16 hi = __float2bfloat16(x);
    __nv_bfloat16 lo = __float2bfloat16(x - __bfloat162float(hi));
    size_t r = (size_t)m * (3 * K);
    Yd[r + k]         = hi;
    Yd[r + K + k]     = lo;
    Yd[r + 2 * K + k] = hi;
}

// ---------------- mma / cp.async helpers ----------------
__device__ __forceinline__ void mma16816(float* c, const unsigned* a, const unsigned* b)
{
    asm volatile(
        "mma.sync.aligned.m16n8k16.row.col.f32.bf16.bf16.f32 "
        "{%0,%1,%2,%3}, {%4,%5,%6,%7}, {%8,%9}, {%0,%1,%2,%3};\n"
        : "+f"(c[0]), "+f"(c[1]), "+f"(c[2]), "+f"(c[3])
        : "r"(a[0]), "r"(a[1]), "r"(a[2]), "r"(a[3]), "r"(b[0]), "r"(b[1]));
}
__device__ __forceinline__ void ldsmx4(unsigned* r, unsigned addr)
{
    asm volatile("ldmatrix.sync.aligned.m8n8.x4.shared.b16 {%0,%1,%2,%3}, [%4];"
                 : "=r"(r[0]), "=r"(r[1]), "=r"(r[2]), "=r"(r[3]) : "r"(addr));
}
__device__ __forceinline__ void cpa16(unsigned dst, const void* src)
{
    asm volatile("cp.async.cg.shared.global [%0], [%1], 16;\n" :: "r"(dst), "l"(src));
}
__device__ __forceinline__ void cpa_commit()
{
    asm volatile("cp.async.commit_group;\n");
}
template<int N>
__device__ __forceinline__ void cpa_wait()
{
    asm volatile("cp.async.wait_group %0;\n" :: "n"(N));
}

// split-bf16 store for out_proj epilogue (cat3 row = 2304 bf16: [hi|hi|lo])
__device__ __forceinline__ void split_store2(__nv_bfloat16* C3, int row, int colL,
                                             float s0, float s1)
{
    __nv_bfloat16 h0 = __float2bfloat16(s0);
    __nv_bfloat16 h1 = __float2bfloat16(s1);
    __nv_bfloat16 l0 = __float2bfloat16(s0 - __bfloat162float(h0));
    __nv_bfloat16 l1 = __float2bfloat16(s1 - __bfloat162float(h1));
    __nv_bfloat162 hp; hp.x = h0; hp.y = h1;
    __nv_bfloat162 lp; lp.x = l0; lp.y = l1;
    size_t rb = (size_t)row * 2304;
    *(__nv_bfloat162*)&C3[rb + colL]        = hp;
    *(__nv_bfloat162*)&C3[rb + 768 + colL]  = hp;
    *(__nv_bfloat162*)&C3[rb + 1536 + colL] = lp;
}

// ---------------- 4-stage pipelined bf16 tensor GEMM, BN=128, z-batched ----------
// B fragments loaded via ldmatrix.x4 (two n8 tiles per load).
// EPI: 0 none (fp32 C), 1 +bias (fp32 C), 3 +residual then split-bf16 store to C3
#define SKS 40
#define TILEB (128 * SKS * 2)
#define STAGES 4
template<int EPI>
__global__ __launch_bounds__(256, 2) void bgemm(
    const __nv_bfloat16* __restrict__ A2, int lda, size_t zsA,
    const __nv_bfloat16* __restrict__ W2, int K2, size_t zsW,
    const float* __restrict__ bias,
    const float* __restrict__ R, int ldr,
    float* __restrict__ C, int ldc, size_t zsC,
    __nv_bfloat16* __restrict__ C3, int zDirOff)
{
    extern __shared__ __nv_bfloat16 dsm[];
    __nv_bfloat16* Asm = dsm;
    __nv_bfloat16* Wsm = dsm + STAGES * 128 * SKS;

    int zz = blockIdx.z;
    A2 += (size_t)zz * zsA;
    W2 += (size_t)zz * zsW;
    C  += (size_t)zz * zsC;
    int dirOff = zz * zDirOff;

    int tid = threadIdx.x;
    int lane = tid & 31;
    int warp = tid >> 5;
    int rowBase = blockIdx.y * 128;
    int colBase = blockIdx.x * 128;
    int warpM = (warp >> 2) * 64;
    int warpN = (warp & 3) * 32;

    int r0 = tid >> 2, c0 = (tid & 3) * 8;
    const __nv_bfloat16* Ap0 = A2 + (size_t)(rowBase + r0) * lda + c0;
    const __nv_bfloat16* Ap1 = A2 + (size_t)(rowBase + r0 + 64) * lda + c0;
    const __nv_bfloat16* Wp0 = W2 + (size_t)(colBase + r0) * K2 + c0;
    const __nv_bfloat16* Wp1 = W2 + (size_t)(colBase + r0 + 64) * K2 + c0;

    unsigned sA = (unsigned)__cvta_generic_to_shared(Asm);
    unsigned sW = (unsigned)__cvta_generic_to_shared(Wsm);
    unsigned stA0 = sA + (r0 * SKS + c0) * 2;
    unsigned stA1 = sA + ((r0 + 64) * SKS + c0) * 2;
    unsigned stW0 = sW + (r0 * SKS + c0) * 2;
    unsigned stW1 = sW + ((r0 + 64) * SKS + c0) * 2;

    float acc[4][4][4];
    #pragma unroll
    for (int i = 0; i < 4; i++)
        #pragma unroll
        for (int j = 0; j < 4; j++)
            #pragma unroll
            for (int q = 0; q < 4; q++) acc[i][j][q] = 0.f;

    int l16 = lane & 15;
    unsigned aAddrBase = sA + ((warpM + l16) * SKS + (lane >> 4) * 8) * 2;
    // B x4 addressing: n = (lane&7) + bit4*8, k-half = bit3
    unsigned wAddrBase = sW + ((warpN + (lane & 7) + ((lane >> 4) & 1) * 8) * SKS
                               + ((lane >> 3) & 1) * 8) * 2;

    int nIter = K2 >> 5;

    // prologue: stages 0..2
    cpa16(stA0, Ap0); cpa16(stA1, Ap1);
    cpa16(stW0, Wp0); cpa16(stW1, Wp1);
    cpa_commit();
    #pragma unroll
    for (int pz = 1; pz < STAGES - 1; pz++) {
        unsigned off = pz * TILEB;
        int ko = pz * 32;
        cpa16(stA0 + off, Ap0 + ko); cpa16(stA1 + off, Ap1 + ko);
        cpa16(stW0 + off, Wp0 + ko); cpa16(stW1 + off, Wp1 + ko);
        cpa_commit();
    }

    int bufc = 0, bufn = STAGES - 1;
    for (int it = 0; it < nIter; it++) {
        if (it + 1 < nIter) cpa_wait<2>(); else cpa_wait<0>();
        __syncthreads();
        if (it + STAGES - 1 < nIter) {
            int ko = (it + STAGES - 1) << 5;
            unsigned off = bufn * TILEB;
            cpa16(stA0 + off, Ap0 + ko); cpa16(stA1 + off, Ap1 + ko);
            cpa16(stW0 + off, Wp0 + ko); cpa16(stW1 + off, Wp1 + ko);
            cpa_commit();
        }

        unsigned aB = aAddrBase + bufc * TILEB;
        unsigned wB = wAddrBase + bufc * TILEB;
        #pragma unroll
        for (int kk = 0; kk < 32; kk += 16) {
            unsigned b[4][2];
            #pragma unroll
            for (int jp = 0; jp < 2; jp++) {
                unsigned br[4];
                ldsmx4(br, wB + (jp * 16 * SKS + kk) * 2);
                b[2 * jp][0]     = br[0];
                b[2 * jp][1]     = br[1];
                b[2 * jp + 1][0] = br[2];
                b[2 * jp + 1][1] = br[3];
            }
            #pragma unroll
            for (int i = 0; i < 4; i++) {
                unsigned a[4];
                ldsmx4(a, aB + (i * 16 * SKS + kk) * 2);
                #pragma unroll
                for (int j = 0; j < 4; j++)
                    mma16816(acc[i][j], a, b[j]);
            }
        }
        bufc = (bufc + 1 == STAGES) ? 0 : bufc + 1;
        bufn = (bufn + 1 == STAGES) ? 0 : bufn + 1;
    }

    int erow = lane >> 2;
    int ecol = (lane & 3) * 2;
    #pragma unroll
    for (int i = 0; i < 4; i++) {
        int row = rowBase + warpM + i * 16 + erow;
        #pragma unroll
        for (int j = 0; j < 4; j++) {
            int col = colBase + warpN + j * 8 + ecol;
            float v0 = acc[i][j][0], v1 = acc[i][j][1];
            float v2 = acc[i][j][2], v3 = acc[i][j][3];
            if (EPI == 1) {
                float b0 = bias[col], b1 = bias[col + 1];
                v0 += b0; v1 += b1; v2 += b0; v3 += b1;
            }
            if (EPI == 3) {
                v0 += R[(size_t)row * ldr + col];
                v1 += R[(size_t)row * ldr + col + 1];
                v2 += R[(size_t)(row + 8) * ldr + col];
                v3 += R[(size_t)(row + 8) * ldr + col + 1];
                split_store2(C3, row,     dirOff + col, v0, v1);
                split_store2(C3, row + 8, dirOff + col, v2, v3);
            } else {
                C[(size_t)row * ldc + col]           = v0;
                C[(size_t)row * ldc + col + 1]       = v1;
                C[(size_t)(row + 8) * ldc + col]     = v2;
                C[(size_t)(row + 8) * ldc + col + 1] = v3;
            }
        }
    }
}

// ---------------- fp32 SGEMM (dt GEMM, K=24), z-batched ----------------
__global__ __launch_bounds__(256) void sgemm128_dt(
    const float* __restrict__ A, int lda, size_t zsA,
    const float* __restrict__ W0, const float* __restrict__ W1, int K,
    const float* __restrict__ bias0, const float* __restrict__ bias1,
    float* __restrict__ C, int ldc, size_t zsC)
{
    __shared__ float As[8][128];
    __shared__ float Ws[8][128];
    int zz = blockIdx.z;
    const float* W = zz ? W1 : W0;
    const float* bias = zz ? bias1 : bias0;
    A += (size_t)zz * zsA;
    C += (size_t)zz * zsC;

    int tid = threadIdx.x;
    int rowBase = blockIdx.y * 128;
    int colBase = blockIdx.x * 128;
    int ty = tid >> 4, tx = tid & 15;
    int arow = tid >> 1;
    int ak   = (tid & 1) * 4;

    float acc[8][8];
    #pragma unroll
    for (int i = 0; i < 8; i++)
        #pragma unroll
        for (int j = 0; j < 8; j++) acc[i][j] = 0.f;

    const float* Aptr = A + (size_t)(rowBase + arow) * lda + ak;
    const float* Wptr = W + (size_t)(colBase + arow) * K + ak;

    for (int k0 = 0; k0 < K; k0 += 8) {
        float4 av = *(const float4*)(Aptr + k0);
        float4 wv = *(const float4*)(Wptr + k0);
        __syncthreads();
        As[ak+0][arow] = av.x; As[ak+1][arow] = av.y;
        As[ak+2][arow] = av.z; As[ak+3][arow] = av.w;
        Ws[ak+0][arow] = wv.x; Ws[ak+1][arow] = wv.y;
        Ws[ak+2][arow] = wv.z; Ws[ak+3][arow] = wv.w;
        __syncthreads();
        #pragma unroll
        for (int k = 0; k < 8; k++) {
            float a[8], w[8];
            *(float4*)&a[0] = *(const float4*)&As[k][ty*8];
            *(float4*)&a[4] = *(const float4*)&As[k][ty*8+4];
            *(float4*)&w[0] = *(const float4*)&Ws[k][tx*8];
            *(float4*)&w[4] = *(const float4*)&Ws[k][tx*8+4];
            #pragma unroll
            for (int i = 0; i < 8; i++)
                #pragma unroll
                for (int j = 0; j < 8; j++)
                    acc[i][j] = fmaf(a[i], w[j], acc[i][j]);
        }
    }
    #pragma unroll
    for (int i = 0; i < 8; i++) {
        int row = rowBase + ty * 8 + i;
        #pragma unroll
        for (int j = 0; j < 8; j++) {
            int col = colBase + tx * 8 + j;
            float v = acc[i][j] + bias[col];
            v = (v > 20.f) ? v : log1pf(__expf(v));
            C[(size_t)row * ldc + col] = v;
        }
    }
}

// ---------------- small-N GEMM (x_proj: N=56, K=768), z-batched ----------------
__global__ __launch_bounds__(256) void sgemm_s(
    const float* __restrict__ A, int lda, size_t zsA,
    const float* __restrict__ W0, const float* __restrict__ W1, int K,
    float* __restrict__ C, int ldc, size_t zsC, int N)
{
    __shared__ float As[16][32];
    __shared__ float Ws[16][64];
    int zz = blockIdx.z;
    const float* W = zz ? W1 : W0;
    A += (size_t)zz * zsA;
    C += (size_t)zz * zsC;

    int tid = threadIdx.x;
    int rowBase = blockIdx.y * 32;
    int colBase = blockIdx.x * 64;
    int ty = tid >> 4, tx = tid & 15;
    float acc[2][4] = {{0.f,0.f,0.f,0.f},{0.f,0.f,0.f,0.f}};
    int wn = tid >> 2, wk = (tid & 3) * 4;
    bool wv = (colBase + wn) < N;

    for (int k0 = 0; k0 < K; k0 += 16) {
        __syncthreads();
        #pragma unroll
        for (int i = tid; i < 512; i += 256) {
            int r = i >> 4, k = i & 15;
            As[k][r] = A[(size_t)(rowBase + r) * lda + k0 + k];
        }
        float4 wvv = wv ? *(const float4*)&W[(size_t)(colBase + wn) * K + k0 + wk]
                        : make_float4(0.f,0.f,0.f,0.f);
        Ws[wk+0][wn] = wvv.x; Ws[wk+1][wn] = wvv.y;
        Ws[wk+2][wn] = wvv.z; Ws[wk+3][wn] = wvv.w;
        __syncthreads();
        #pragma unroll
        for (int k = 0; k < 16; k++) {
            float a0 = As[k][ty], a1 = As[k][ty + 16];
            float4 w4 = *(const float4*)&Ws[k][tx*4];
            acc[0][0] = fmaf(a0, w4.x, acc[0][0]);
            acc[0][1] = fmaf(a0, w4.y, acc[0][1]);
            acc[0][2] = fmaf(a0, w4.z, acc[0][2]);
            acc[0][3] = fmaf(a0, w4.w, acc[0][3]);
            acc[1][0] = fmaf(a1, w4.x, acc[1][0]);
            acc[1][1] = fmaf(a1, w4.y, acc[1][1]);
            acc[1][2] = fmaf(a1, w4.z, acc[1][2]);
            acc[1][3] = fmaf(a1, w4.w, acc[1][3]);
        }
    }
    #pragma unroll
    for (int i = 0; i < 2; i++) {
        int row = rowBase + ty + i * 16;
        #pragma unroll
        for (int j = 0; j < 4; j++) {
            int col = colBase + tx * 4 + j;
            if (col < N) C[(size_t)row * ldc + col] = acc[i][j];
        }
    }
}

// ---------------- causal depthwise conv (k=4) + SiLU, z-batched ----------------
__global__ void conv_kernel(const float* __restrict__ XZ,
                            const float* __restrict__ Wc0, const float* __restrict__ Bc0,
                            const float* __restrict__ Wc1, const float* __restrict__ Bc1,
                            float* __restrict__ XC)
{
    int idx = blockIdx.x * blockDim.x + threadIdx.x;
    if (idx >= ROWS * DI) return;
    int dir = blockIdx.y;
    const float* Wc = dir ? Wc1 : Wc0;
    const float* Bc = dir ? Bc1 : Bc0;
    const float* XZd = XZ + (size_t)dir * ZS_XZ;
    float* XCd = XC + (size_t)dir * ZS_XC;

    int d = idx % DI;
    int t = (idx / DI) % LSEQ;
    int b = idx / (DI * LSEQ);
    const float* xm = XZd + (size_t)b * LSEQ * (2 * DI) + d;
    float acc = Bc[d];
    #pragma unroll
    for (int j = 0; j < 4; j++) {
        int tt = (dir == 0) ? (t - 3 + j) : (t + 3 - j);
        if (tt >= 0 && tt < LSEQ)
            acc = fmaf(Wc[d * 4 + j], xm[(size_t)tt * (2 * DI)], acc);
    }
    acc = acc / (1.f + __expf(-acc));
    XCd[idx] = acc;
}

// ---------------- selective scan, z-batched: grid (NB, 12, 2) ----------------
__global__ __launch_bounds__(64) void scan_kernel(
    const float* __restrict__ XC,
    const float* __restrict__ DT,
    const float* __restrict__ XDBL,
    const float* __restrict__ XZ,
    const float* __restrict__ Alog0, const float* __restrict__ Dp0,
    const float* __restrict__ Alog1, const float* __restrict__ Dp1,
    __nv_bfloat16* __restrict__ A3)
{
    __shared__ float Bs[LSEQ][DS];
    __shared__ float Cs[LSEQ][DS];
    int b = blockIdx.x;
    int dir = blockIdx.z;
    int d = blockIdx.y * 64 + threadIdx.x;

    const float* Alog = dir ? Alog1 : Alog0;
    const float* Dp   = dir ? Dp1 : Dp0;
    const float* XCd   = XC + (size_t)dir * ZS_XC;
    const float* DTd   = DT + (size_t)dir * ZS_DT;
    const float* XDBLd = XDBL + (size_t)dir * ZS_XD;
    const float* XZd   = XZ + (size_t)dir * ZS_XZ;
    __nv_bfloat16* A3d = A3 + (size_t)dir * ZS_A3;

    const float* xd = XDBLd + (size_t)b * LSEQ * XPD;
    for (int i = threadIdx.x; i < LSEQ * DS; i += 64) {
        int t = i / DS, n = i % DS;
        Bs[t][n] = xd[t * XPD + DTRK + n];
        Cs[t][n] = xd[t * XPD + DTRK + DS + n];
    }
    __syncthreads();

    float A[DS];
    #pragma unroll
    for (int n = 0; n < DS; n++) A[n] = -__expf(Alog[d * DS + n]);
    float Dd = Dp[d];
    float h[DS];
    #pragma unroll
    for (int n = 0; n < DS; n++) h[n] = 0.f;

    const float* ub  = XCd + (size_t)b * LSEQ * DI + d;
    const float* dtb = DTd + (size_t)b * LSEQ * DI + d;
    const float* zb  = XZd + (size_t)b * LSEQ * (2 * DI) + DI + d;

    int t = dir ? (LSEQ - 1) : 0;
    int step = dir ? -1 : 1;
    float dtv = dtb[(size_t)t * DI];
    float u   = ub[(size_t)t * DI];
    float z   = zb[(size_t)t * (2 * DI)];

    for (int s = 0; s < LSEQ; s++) {
        int tn = t + step;
        float dtn = 0.f, un = 0.f, zn = 0.f;
        if (s + 1 < LSEQ) {
            dtn = dtb[(size_t)tn * DI];
            un  = ub[(size_t)tn * DI];
            zn  = zb[(size_t)tn * (2 * DI)];
        }

        float du = dtv * u;
        float accv = 0.f;
        #pragma unroll
        for (int n = 0; n < DS; n++) {
            float dA = __expf(dtv * A[n]);
            h[n] = fmaf(dA, h[n], du * Bs[t][n]);
            accv = fmaf(h[n], Cs[t][n], accv);
        }
        float sz = z / (1.f + __expf(-z));
        float y = (accv + u * Dd) * sz;
        __nv_bfloat16 hi = __float2bfloat16(y);
        __nv_bfloat16 lo = __float2bfloat16(y - __bfloat162float(hi));
        size_t rb = ((size_t)b * LSEQ + t) * (3 * DI);
        A3d[rb + d]          = hi;
        A3d[rb + DI + d]     = hi;
        A3d[rb + 2 * DI + d] = lo;

        dtv = dtn; u = un; z = zn; t = tn;
    }
}

// ---------------- final scatter ----------------
__global__ void final_kernel(const float* __restrict__ X,
                             const float* __restrict__ FUSED,
                             const int* __restrict__ inv_idx,
                             float* __restrict__ OUT)
{
    int idx = blockIdx.x * blockDim.x + threadIdx.x;
    if (idx >= NB * SEQF * DM) return;
    int c = idx % DM;
    int s = (idx / DM) % SEQF;
    int b = idx / (DM * SEQF);
    if (s == 0) {
        OUT[idx] = X[idx];
    } else {
        int src = inv_idx[s - 1];
        OUT[idx] = FUSED[((size_t)b * LSEQ + src) * DM + c];
    }
}

// ---------------- host launch ----------------
extern "C" void kernel_launch(void* const* d_in, const int* in_sizes, int n_in,
                              void* d_out, int out_size)
{
    float* S = nullptr;
    cudaGetSymbolAddress((void**)&S, g_scratch);

    float* pr    = S + OFF_PR;
    float* xz    = S + OFF_XZ;
    float* xc    = S + OFF_XC;
    float* xdbl  = S + OFF_XDBL;
    float* dtb   = S + OFF_DT;
    float* fused = S + OFF_FUSED;
    __nv_bfloat16* a3    = (__nv_bfloat16*)(S + OFF_ACT3);
    __nv_bfloat16* cat3  = (__nv_bfloat16*)(S + OFF_CAT3);
    __nv_bfloat16* w3in  = (__nv_bfloat16*)(S + OFF_W3IN);
    __nv_bfloat16* w3out = (__nv_bfloat16*)(S + OFF_W3OUT);
    __nv_bfloat16* w3fus = (__nv_bfloat16*)(S + OFF_W3FUS);

    const int SMEM_BG = STAGES * 128 * SKS * 2 * 2;   // 81920
    cudaFuncSetAttribute(bgemm<0>, cudaFuncAttributeMaxDynamicSharedMemorySize, SMEM_BG);
    cudaFuncSetAttribute(bgemm<1>, cudaFuncAttributeMaxDynamicSharedMemorySize, SMEM_BG);
    cudaFuncSetAttribute(bgemm<3>, cudaFuncAttributeMaxDynamicSharedMemorySize, SMEM_BG);

    const float* x        = (const float*)d_in[0];
    const float* f_ln_g   = (const float*)d_in[1];
    const float* f_ln_b   = (const float*)d_in[2];
    const float* f_in_w   = (const float*)d_in[3];
    const float* f_conv_w = (const float*)d_in[4];
    const float* f_conv_b = (const float*)d_in[5];
    const float* f_x_w    = (const float*)d_in[6];
    const float* f_dt_w   = (const float*)d_in[7];
    const float* f_dt_b   = (const float*)d_in[8];
    const float* f_A_log  = (const float*)d_in[9];
    const float* f_Dp     = (const float*)d_in[10];
    const float* f_out_w  = (const float*)d_in[11];
    const float* b_ln_g   = (const float*)d_in[12];
    const float* b_ln_b   = (const float*)d_in[13];
    const float* b_in_w   = (const float*)d_in[14];
    const float* b_conv_w = (const float*)d_in[15];
    const float* b_conv_b = (const float*)d_in[16];
    const float* b_x_w    = (const float*)d_in[17];
    const float* b_dt_w   = (const float*)d_in[18];
    const float* b_dt_b   = (const float*)d_in[19];
    const float* b_A_log  = (const float*)d_in[20];
    const float* b_Dp     = (const float*)d_in[21];
    const float* b_out_w  = (const float*)d_in[22];
    const float* fusion_w = (const float*)d_in[23];
    const float* fusion_b = (const float*)d_in[24];
    const int*   scan_idx = (const int*)d_in[25];
    const int*   inv_idx  = (const int*)d_in[26];

    gather_kernel<<<(ROWS*DM + 255)/256, 256>>>(x, scan_idx, pr);

    ln_split_kernel<<<dim3(ROWS, 2), 128>>>(pr, f_ln_g, f_ln_b, b_ln_g, b_ln_b, a3);

    split3_wt2<<<dim3((2*DI*DM + 255)/256, 2), 256>>>(f_in_w, b_in_w, w3in,
                                                      2*DI*DM, DM, ZS_W3IN);
    split3_wt2<<<dim3((DM*DI + 255)/256, 2), 256>>>(f_out_w, b_out_w, w3out,
                                                    DM*DI, DI, ZS_W3OUT);
    split3_wt2<<<dim3((DM*DI + 255)/256, 1), 256>>>(fusion_w, fusion_w, w3fus,
                                                    DM*DI, DI, 0);

    // in_proj both dirs: (K'=1152, N=1536)
    bgemm<0><<<dim3(12, 48, 2), 256, SMEM_BG>>>(a3, 3*DM, ZS_A3,
                                                w3in, 3*DM, ZS_W3IN,
                                                nullptr, nullptr, 0,
                                                xz, 2*DI, ZS_XZ,
                                                nullptr, 0);

    conv_kernel<<<dim3((ROWS*DI + 255)/256, 2), 256>>>(xz, f_conv_w, f_conv_b,
                                                       b_conv_w, b_conv_b, xc);

    sgemm_s<<<dim3(1, ROWS/32, 2), 256>>>(xc, DI, ZS_XC, f_x_w, b_x_w, DI,
                                          xdbl, XPD, ZS_XD, XPD);

    sgemm128_dt<<<dim3(6, 48, 2), 256>>>(xdbl, XPD, ZS_XD, f_dt_w, b_dt_w, DTRK,
                                         f_dt_b, b_dt_b, dtb, DI, ZS_DT);

    scan_kernel<<<dim3(NB, 12, 2), 64>>>(xc, dtb, xdbl, xz,
                                         f_A_log, f_Dp, b_A_log, b_Dp, a3);

    // out_proj both dirs: (K'=2304, N=384) -> cat3 (cols offset z*384)
    bgemm<3><<<dim3(3, 48, 2), 256, SMEM_BG>>>(a3, 3*DI, ZS_A3,
                                               w3out, 3*DI, ZS_W3OUT,
                                               nullptr, pr, DM,
                                               nullptr, 0, 0,
                                               cat3, DM);

    // fusion: (K'=2304, N=384)
    bgemm<1><<<dim3(3, 48, 1), 256, SMEM_BG>>>(cat3, 2304, 0,
                                               w3fus, 3*(2*DM), 0,
                                               fusion_b, nullptr, 0,
                                               fused, DM, 0,
                                               nullptr, 0);

    final_kernel<<<(NB*SEQF*DM + 255)/256, 256>>>(x, fused, inv_idx, (float*)d_out);
}